// round 13
// baseline (speedup 1.0000x reference)
#include <cuda_runtime.h>
#include <math.h>

#define Nq   20000
#define KK   48
#define PADK 68
#define BST  140   // B2 ull row stride (conflict-free: 140 mod 16 = 12)

// ---- scratch ----
__device__ float  g_q[Nq * 64];
__device__ float  g_ctx[Nq * 64];
__device__ float  g_att[Nq * 64];
__device__ float  g_hid[Nq * 256];
__device__ float  g_x[Nq * 64];
__device__ float  g_z[Nq * 64];
__device__ double g_sum1[64], g_sq1[64];
__device__ double g_sum2[64], g_sq2[64];
// pre-converted tf32 weights (padded layouts)
__device__ unsigned long long g_B2d[32 * BST];
__device__ unsigned g_Wq[64 * 72];
__device__ unsigned g_Wo[64 * 72];
__device__ unsigned g_W1[64 * 264];
__device__ unsigned g_W2[256 * 72];
__device__ unsigned g_Wl[64 * 72];

__device__ __forceinline__ unsigned f2tf32(float x) {
    unsigned r; asm("cvt.rna.tf32.f32 %0, %1;" : "=r"(r) : "f"(x)); return r;
}
__device__ __forceinline__ void mma_tf32(float& d0, float& d1, float& d2, float& d3,
                                         unsigned a0, unsigned a1, unsigned a2, unsigned a3,
                                         unsigned b0, unsigned b1) {
    asm volatile("mma.sync.aligned.m16n8k8.row.col.f32.tf32.tf32.f32 "
                 "{%0,%1,%2,%3}, {%4,%5,%6,%7}, {%8,%9}, {%0,%1,%2,%3};"
                 : "+f"(d0), "+f"(d1), "+f"(d2), "+f"(d3)
                 : "r"(a0), "r"(a1), "r"(a2), "r"(a3), "r"(b0), "r"(b1));
}

// ============================================================================
// prep: convert weights to tf32 padded layouts (once per launch)
// ============================================================================
__global__ __launch_bounds__(256) void prep_kernel(
    const float* __restrict__ in_w,  const float* __restrict__ out_w,
    const float* __restrict__ lin1_w, const float* __restrict__ lin2_w,
    const float* __restrict__ outl_w)
{
    const int tid = threadIdx.x, b = blockIdx.x;
    if (b == 0) {
        for (int i = tid; i < 4096; i += 256) {
            int n = i >> 6, k = i & 63;
            g_Wq[k * 72 + n] = f2tf32(in_w[n * 64 + k]);
        }
    } else if (b <= 2) {             // B2: in_w rows 64..191 (K|V), packed pairs
        for (int i = (b - 1) * 4096 + tid; i < b * 4096; i += 256) {
            int n = i >> 6, k = i & 63;
            int ks = k >> 3, rem = k & 7, tg = rem & 3, slot = rem >> 2;
            ((unsigned*)g_B2d)[(((ks*4+tg)*BST) + n) * 2 + slot] = f2tf32(in_w[4096 + i]);
        }
    } else if (b == 3) {
        for (int i = tid; i < 4096; i += 256) {
            int n = i >> 6, k = i & 63;
            g_Wo[k * 72 + n] = f2tf32(out_w[n * 64 + k]);
        }
    } else if (b <= 7) {
        for (int i = (b - 4) * 4096 + tid; i < (b - 3) * 4096; i += 256) {
            int n = i >> 6, k = i & 63;
            g_W1[k * 264 + n] = f2tf32(lin1_w[n * 64 + k]);
        }
    } else if (b <= 11) {
        for (int i = (b - 8) * 4096 + tid; i < (b - 7) * 4096; i += 256) {
            int k = i >> 6, n = i & 63;
            g_W2[k * 72 + n] = f2tf32(lin2_w[n * 256 + k]);
        }
    } else {
        for (int i = tid; i < 4096; i += 256) {
            int n = i >> 6, k = i & 63;
            g_Wl[k * 72 + n] = f2tf32(outl_w[n * 64 + k]);
        }
    }
}

__global__ void zero_stats() {
    int t = threadIdx.x;
    if (t < 64) { g_sum1[t] = 0.0; g_sq1[t] = 0.0; g_sum2[t] = 0.0; g_sq2[t] = 0.0; }
}

// ============================================================================
// qproj
// ============================================================================
#define SM_Q ((64 * 72 + 128 * PADK) * 4)
__global__ __launch_bounds__(256) void qproj_mma(
    const float* __restrict__ qc, const float* __restrict__ q_w, const float* __restrict__ q_b,
    const float* __restrict__ in_b)
{
    extern __shared__ unsigned sm[];
    unsigned* s_W = sm;
    unsigned* s_A = sm + 64 * 72;
    const int tid = threadIdx.x, lane = tid & 31, w = tid >> 5;
    const int g = lane >> 2, tig = lane & 3, mr = w * 16;
    const int rows0 = blockIdx.x * 128;

    for (int i = tid; i < 1152; i += 256)
        ((uint4*)s_W)[i] = ((const uint4*)g_Wq)[i];
    {
        const int c = tid & 63;
        const float w0 = q_w[c*3], w1 = q_w[c*3+1], w2 = q_w[c*3+2], b = q_b[c];
        for (int i = tid; i < 128 * 64; i += 256) {
            int r = i >> 6, row = rows0 + r;
            float v = 0.f;
            if (row < Nq)
                v = fmaxf(b + w0*qc[row*3] + w1*qc[row*3+1] + w2*qc[row*3+2], 0.f);
            s_A[r * PADK + c] = f2tf32(v);
        }
    }
    __syncthreads();

    float acc[8][4] = {};
    #pragma unroll
    for (int ks = 0; ks < 8; ++ks) {
        int k0 = ks * 8;
        unsigned a0 = s_A[(mr+g)*PADK + k0 + tig];
        unsigned a1 = s_A[(mr+g+8)*PADK + k0 + tig];
        unsigned a2 = s_A[(mr+g)*PADK + k0 + tig + 4];
        unsigned a3 = s_A[(mr+g+8)*PADK + k0 + tig + 4];
        #pragma unroll
        for (int nt = 0; nt < 8; ++nt) {
            unsigned b0 = s_W[(k0+tig)*72 + nt*8 + g];
            unsigned b1 = s_W[(k0+tig+4)*72 + nt*8 + g];
            mma_tf32(acc[nt][0], acc[nt][1], acc[nt][2], acc[nt][3], a0, a1, a2, a3, b0, b1);
        }
    }
    #pragma unroll
    for (int nt = 0; nt < 8; ++nt) {
        int col = nt*8 + 2*tig;
        float b0 = in_b[col], b1 = in_b[col+1];
        int r0 = rows0 + mr + g, r1 = r0 + 8;
        if (r0 < Nq) { float2 o = {(acc[nt][0]+b0)*0.25f, (acc[nt][1]+b1)*0.25f};
                       *(float2*)(g_q + r0*64 + col) = o; }
        if (r1 < Nq) { float2 o = {(acc[nt][2]+b0)*0.25f, (acc[nt][3]+b1)*0.25f};
                       *(float2*)(g_q + r1*64 + col) = o; }
    }
}

// ============================================================================
// attention kernel (PERSISTENT): loops over query groups of 4; B2 staged once.
// 384 threads (12 warps), N-split: warps 0-5 K half, 6-11 V half, M=32/warp.
// ============================================================================
#define SMEM_ATTN ((13056 + 8960 + 256 + 768 + 576 + 192) * 4)
__global__ __launch_bounds__(384, 2) void attn_kernel(
    const float* __restrict__ vf,     const float* __restrict__ vc,
    const float* __restrict__ qc,     const int*   __restrict__ kidx,
    const float* __restrict__ kpos_w, const float* __restrict__ kpos_b,
    const float* __restrict__ in_b)
{
    extern __shared__ unsigned smu[];
    unsigned* s_kfu = smu;                         // [192][68] tf32 A (alias vp float)
    unsigned* s_B2  = smu + 192 * PADK;            // ull[32][140] = 8960 words
    float*    s_q   = (float*)(s_B2 + 8960);       // 256
    float*    s_sc  = s_q + 256;                   // 768
    float*    s_rel = s_sc + 768;                  // 576
    int*      s_idx = (int*)(s_rel + 576);         // 192

    const int tid  = threadIdx.x;
    const int lane = tid & 31;
    const int w    = tid >> 5;            // 0..11

    // ---- stage B2 once per CTA ----
    for (int i = tid; i < 2240; i += 384)
        ((uint4*)s_B2)[i] = ((const uint4*)g_B2d)[i];

    const int g    = lane >> 2;
    const int tig  = lane & 3;
    const int half = (w >= 6);
    const int mw   = w - half * 6;
    const int mr   = mw * 32;
    const int cb   = half * 64;
    const unsigned long long* B2u = (const unsigned long long*)s_B2;

    // loop-invariant gather coefficients (this thread always handles column pair c2)
    const int c2 = (tid & 31) * 2;
    const float ka0 = kpos_w[c2*3],   ka1 = kpos_w[c2*3+1], ka2 = kpos_w[c2*3+2];
    const float kb0 = kpos_w[c2*3+3], kb1 = kpos_w[c2*3+4], kb2 = kpos_w[c2*3+5];
    const float kba = kpos_b[c2], kbb = kpos_b[c2+1];

    for (int grp = blockIdx.x; grp < Nq / 4; grp += gridDim.x) {
        const int n0 = grp * 4;

        // ---- stage idx/rel/q ----
        if (tid < 192) {
            int q = tid / KK, kk = tid - q * KK;
            int n = n0 + q;
            int idx = kidx[n * KK + kk];
            s_idx[tid] = idx;
            int safe = idx < 0 ? 0 : idx;
            s_rel[tid*3+0] = vc[safe*3+0] - qc[n*3+0];
            s_rel[tid*3+1] = vc[safe*3+1] - qc[n*3+1];
            s_rel[tid*3+2] = vc[safe*3+2] - qc[n*3+2];
        }
        if (tid < 256) s_q[tid] = g_q[(n0 + (tid >> 6)) * 64 + (tid & 63)];
        __syncthreads();

        // ---- gather key features (tf32, float2-vectorized) ----
        for (int e = tid; e < 192 * 32; e += 384) {
            int kg = e >> 5;
            int idx = s_idx[kg]; if (idx < 0) idx = 0;
            float2 f = *(const float2*)(vf + idx * 64 + c2);
            float r0 = s_rel[kg*3], r1 = s_rel[kg*3+1], r2 = s_rel[kg*3+2];
            float p0 = kba + ka0*r0 + ka1*r1 + ka2*r2;
            float p1 = kbb + kb0*r0 + kb1*r1 + kb2*r2;
            uint2 o = { f2tf32(f.x + fmaxf(p0, 0.f)), f2tf32(f.y + fmaxf(p1, 0.f)) };
            *(uint2*)(s_kfu + kg * PADK + c2) = o;
        }
        __syncthreads();

        // ---- MMA mainloop ----
        float acc0[8][4], acc1[8][4];
        #pragma unroll
        for (int nt = 0; nt < 8; ++nt) {
            int cc = 8*nt + 2*tig;
            float b0 = in_b[64 + cb + cc], b1 = in_b[64 + cb + cc + 1];
            acc0[nt][0] = b0; acc0[nt][1] = b1; acc0[nt][2] = b0; acc0[nt][3] = b1;
            acc1[nt][0] = b0; acc1[nt][1] = b1; acc1[nt][2] = b0; acc1[nt][3] = b1;
        }
        #pragma unroll
        for (int ks = 0; ks < 8; ++ks) {
            const int k0 = ks * 8;
            unsigned a00 = s_kfu[(mr+g)*PADK + k0 + tig];
            unsigned a01 = s_kfu[(mr+g+8)*PADK + k0 + tig];
            unsigned a02 = s_kfu[(mr+g)*PADK + k0 + tig + 4];
            unsigned a03 = s_kfu[(mr+g+8)*PADK + k0 + tig + 4];
            unsigned a10 = s_kfu[(mr+g+16)*PADK + k0 + tig];
            unsigned a11 = s_kfu[(mr+g+24)*PADK + k0 + tig];
            unsigned a12 = s_kfu[(mr+g+16)*PADK + k0 + tig + 4];
            unsigned a13 = s_kfu[(mr+g+24)*PADK + k0 + tig + 4];
            const unsigned long long* bp = B2u + (ks*4 + tig) * BST + g + cb;
            #pragma unroll
            for (int nt = 0; nt < 8; ++nt) {
                unsigned long long pv = bp[nt * 8];
                unsigned b0 = (unsigned)pv, b1 = (unsigned)(pv >> 32);
                mma_tf32(acc0[nt][0], acc0[nt][1], acc0[nt][2], acc0[nt][3],
                         a00, a01, a02, a03, b0, b1);
                mma_tf32(acc1[nt][0], acc1[nt][1], acc1[nt][2], acc1[nt][3],
                         a10, a11, a12, a13, b0, b1);
            }
        }
        __syncthreads();   // all A reads complete before vp aliases kf

        if (half == 0) {
            #pragma unroll
            for (int t = 0; t < 2; ++t) {
                int r1 = mr + 16*t + g, r2 = r1 + 8;
                int q1 = r1 / KK, kk1 = r1 - q1 * KK;
                int q2 = r2 / KK, kk2 = r2 - q2 * KK;
                #pragma unroll
                for (int h = 0; h < 4; ++h) {
                    int nA = 2*h, nB = 2*h + 1;
                    int cA = 8*nA + 2*tig, cB = 8*nB + 2*tig;
                    float qA0 = s_q[q1*64+cA], qA1 = s_q[q1*64+cA+1];
                    float qB0 = s_q[q1*64+cB], qB1 = s_q[q1*64+cB+1];
                    float qC0 = s_q[q2*64+cA], qC1 = s_q[q2*64+cA+1];
                    float qD0 = s_q[q2*64+cB], qD1 = s_q[q2*64+cB+1];
                    float s0, s1;
                    if (t == 0) {
                        s0 = acc0[nA][0]*qA0 + acc0[nA][1]*qA1 + acc0[nB][0]*qB0 + acc0[nB][1]*qB1;
                        s1 = acc0[nA][2]*qC0 + acc0[nA][3]*qC1 + acc0[nB][2]*qD0 + acc0[nB][3]*qD1;
                    } else {
                        s0 = acc1[nA][0]*qA0 + acc1[nA][1]*qA1 + acc1[nB][0]*qB0 + acc1[nB][1]*qB1;
                        s1 = acc1[nA][2]*qC0 + acc1[nA][3]*qC1 + acc1[nB][2]*qD0 + acc1[nB][3]*qD1;
                    }
                    s0 += __shfl_xor_sync(0xffffffffu, s0, 1);
                    s0 += __shfl_xor_sync(0xffffffffu, s0, 2);
                    s1 += __shfl_xor_sync(0xffffffffu, s1, 1);
                    s1 += __shfl_xor_sync(0xffffffffu, s1, 2);
                    if (tig == 0) {
                        s_sc[(q1*4+h)*48 + kk1] = (s_idx[r1] < 0) ? -1e30f : s0;
                        s_sc[(q2*4+h)*48 + kk2] = (s_idx[r2] < 0) ? -1e30f : s1;
                    }
                }
            }
        } else {
            float* s_vp = (float*)s_kfu;
            #pragma unroll
            for (int t = 0; t < 2; ++t) {
                int r1 = mr + 16*t + g, r2 = r1 + 8;
                #pragma unroll
                for (int nt = 0; nt < 8; ++nt) {
                    int cc = 8*nt + 2*tig;
                    float2 o1, o2;
                    if (t == 0) { o1 = make_float2(acc0[nt][0], acc0[nt][1]);
                                  o2 = make_float2(acc0[nt][2], acc0[nt][3]); }
                    else        { o1 = make_float2(acc1[nt][0], acc1[nt][1]);
                                  o2 = make_float2(acc1[nt][2], acc1[nt][3]); }
                    *(float2*)(s_vp + r1*PADK + cc) = o1;
                    *(float2*)(s_vp + r2*PADK + cc) = o2;
                }
            }
        }
        __syncthreads();

        // ---- softmax (16 (q,h) rows over 12 warps) ----
        for (int r = w; r < 16; r += 12) {
            float* sc = s_sc + r * 48;
            float v0 = sc[lane];
            float v1 = (lane < 16) ? sc[32 + lane] : -1e30f;
            float m = fmaxf(v0, v1);
            #pragma unroll
            for (int o = 16; o > 0; o >>= 1) m = fmaxf(m, __shfl_xor_sync(0xffffffffu, m, o));
            float e0 = __expf(v0 - m);
            float e1 = (lane < 16) ? __expf(v1 - m) : 0.f;
            float s = e0 + e1;
            #pragma unroll
            for (int o = 16; o > 0; o >>= 1) s += __shfl_xor_sync(0xffffffffu, s, o);
            float inv = 1.f / s;
            sc[lane] = e0 * inv;
            if (lane < 16) sc[32 + lane] = e1 * inv;
        }
        __syncthreads();

        // ---- ctx = attn @ V -> g_ctx ----
        {
            const float* s_vp = (const float*)s_kfu;
            if (tid < 256) {
                int q = tid >> 6, c = tid & 63, h = c >> 4;
                const float* a  = s_sc + (q * 4 + h) * 48;
                const float* vp = s_vp + (q * 48) * PADK + c;
                float acc2 = 0.f;
                #pragma unroll 8
                for (int kk = 0; kk < KK; ++kk) acc2 = fmaf(a[kk], vp[kk * PADK], acc2);
                g_ctx[(n0 + q) * 64 + c] = acc2;
            }
        }
        __syncthreads();   // vp/sc reads done before next iteration's writes
    }
}

// ============================================================================
// ffn1: g_att = g_ctx @ out_w^T + out_b
// ============================================================================
#define SM_F1 ((64 * 72 + 128 * PADK) * 4)
__global__ __launch_bounds__(256) void ffn1_mma(const float* __restrict__ out_b)
{
    extern __shared__ unsigned sm[];
    unsigned* s_W = sm;
    unsigned* s_A = sm + 64 * 72;
    const int tid = threadIdx.x, lane = tid & 31, w = tid >> 5;
    const int g = lane >> 2, tig = lane & 3, mr = w * 16;
    const int rows0 = blockIdx.x * 128;

    for (int i = tid; i < 1152; i += 256)
        ((uint4*)s_W)[i] = ((const uint4*)g_Wo)[i];
    for (int i = tid; i < 128 * 64; i += 256) {
        int r = i >> 6, c = i & 63, row = rows0 + r;
        s_A[r * PADK + c] = f2tf32(row < Nq ? g_ctx[row * 64 + c] : 0.f);
    }
    __syncthreads();

    float acc[8][4] = {};
    #pragma unroll
    for (int ks = 0; ks < 8; ++ks) {
        int k0 = ks * 8;
        unsigned a0 = s_A[(mr+g)*PADK + k0 + tig];
        unsigned a1 = s_A[(mr+g+8)*PADK + k0 + tig];
        unsigned a2 = s_A[(mr+g)*PADK + k0 + tig + 4];
        unsigned a3 = s_A[(mr+g+8)*PADK + k0 + tig + 4];
        #pragma unroll
        for (int nt = 0; nt < 8; ++nt) {
            unsigned b0 = s_W[(k0+tig)*72 + nt*8 + g];
            unsigned b1 = s_W[(k0+tig+4)*72 + nt*8 + g];
            mma_tf32(acc[nt][0], acc[nt][1], acc[nt][2], acc[nt][3], a0, a1, a2, a3, b0, b1);
        }
    }
    #pragma unroll
    for (int nt = 0; nt < 8; ++nt) {
        int col = nt*8 + 2*tig;
        float b0 = out_b[col], b1 = out_b[col+1];
        int r0 = rows0 + mr + g, r1 = r0 + 8;
        if (r0 < Nq) { float2 o = {acc[nt][0]+b0, acc[nt][1]+b1};
                       *(float2*)(g_att + r0*64 + col) = o; }
        if (r1 < Nq) { float2 o = {acc[nt][2]+b0, acc[nt][3]+b1};
                       *(float2*)(g_att + r1*64 + col) = o; }
    }
}

// ============================================================================
// ffn2: g_hid = relu(g_att @ lin1_w^T + lin1_b)
// ============================================================================
#define SM_F2 ((64 * 264 + 64 * PADK) * 4)
__global__ __launch_bounds__(256) void ffn2_mma(const float* __restrict__ lin1_b)
{
    extern __shared__ unsigned sm[];
    unsigned* s_W = sm;              // [64][264]
    unsigned* s_A = sm + 64 * 264;   // [64][68]
    const int tid = threadIdx.x, lane = tid & 31, w = tid >> 5;
    const int g = lane >> 2, tig = lane & 3;
    const int mr = (w & 3) * 16, nbase = (w >> 2) * 128;
    const int rows0 = blockIdx.x * 64;

    for (int i = tid; i < 4224; i += 256)
        ((uint4*)s_W)[i] = ((const uint4*)g_W1)[i];
    for (int i = tid; i < 64 * 64; i += 256) {
        int r = i >> 6, c = i & 63, row = rows0 + r;
        s_A[r * PADK + c] = f2tf32(row < Nq ? g_att[row * 64 + c] : 0.f);
    }
    __syncthreads();

    float acc[16][4];
    #pragma unroll
    for (int nt = 0; nt < 16; ++nt)
        #pragma unroll
        for (int j = 0; j < 4; ++j) acc[nt][j] = 0.f;

    #pragma unroll
    for (int ks = 0; ks < 8; ++ks) {
        int k0 = ks * 8;
        unsigned a0 = s_A[(mr+g)*PADK + k0 + tig];
        unsigned a1 = s_A[(mr+g+8)*PADK + k0 + tig];
        unsigned a2 = s_A[(mr+g)*PADK + k0 + tig + 4];
        unsigned a3 = s_A[(mr+g+8)*PADK + k0 + tig + 4];
        #pragma unroll
        for (int nt = 0; nt < 16; ++nt) {
            unsigned b0 = s_W[(k0+tig)*264 + nbase + nt*8 + g];
            unsigned b1 = s_W[(k0+tig+4)*264 + nbase + nt*8 + g];
            mma_tf32(acc[nt][0], acc[nt][1], acc[nt][2], acc[nt][3], a0, a1, a2, a3, b0, b1);
        }
    }
    #pragma unroll
    for (int nt = 0; nt < 16; ++nt) {
        int col = nbase + nt*8 + 2*tig;
        float b0 = lin1_b[col], b1 = lin1_b[col+1];
        int r0 = rows0 + mr + g, r1 = r0 + 8;
        if (r0 < Nq) { float2 o = {fmaxf(acc[nt][0]+b0, 0.f), fmaxf(acc[nt][1]+b1, 0.f)};
                       *(float2*)(g_hid + r0*256 + col) = o; }
        if (r1 < Nq) { float2 o = {fmaxf(acc[nt][2]+b0, 0.f), fmaxf(acc[nt][3]+b1, 0.f)};
                       *(float2*)(g_hid + r1*256 + col) = o; }
    }
}

// ============================================================================
// ffn3: g_x = g_att + g_hid @ lin2_w^T + lin2_b, BN1 stats
// ============================================================================
#define SM_F3 ((256 * 72 + 128 * PADK + 128) * 4)
__global__ __launch_bounds__(256) void ffn3_mma(const float* __restrict__ lin2_b)
{
    extern __shared__ unsigned sm[];
    unsigned* s_W = sm;               // [256][72]
    unsigned* s_A = sm + 256 * 72;    // [128][68]
    float* s_ps = (float*)(s_A + 128 * PADK);
    float* s_pq = s_ps + 64;
    const int tid = threadIdx.x, lane = tid & 31, w = tid >> 5;
    const int g = lane >> 2, tig = lane & 3, mr = w * 16;
    const int rows0 = blockIdx.x * 128;

    if (tid < 64) { s_ps[tid] = 0.f; s_pq[tid] = 0.f; }
    for (int i = tid; i < 4608; i += 256)
        ((uint4*)s_W)[i] = ((const uint4*)g_W2)[i];

    float acc[8][4] = {};
    for (int kc = 0; kc < 4; ++kc) {
        __syncthreads();
        for (int i = tid; i < 128 * 64; i += 256) {
            int r = i >> 6, c = i & 63, row = rows0 + r;
            s_A[r * PADK + c] = f2tf32(row < Nq ? g_hid[row * 256 + kc * 64 + c] : 0.f);
        }
        __syncthreads();
        #pragma unroll
        for (int ks = 0; ks < 8; ++ks) {
            int k0 = ks * 8;
            unsigned a0 = s_A[(mr+g)*PADK + k0 + tig];
            unsigned a1 = s_A[(mr+g+8)*PADK + k0 + tig];
            unsigned a2 = s_A[(mr+g)*PADK + k0 + tig + 4];
            unsigned a3 = s_A[(mr+g+8)*PADK + k0 + tig + 4];
            int kw = kc * 64 + k0;
            #pragma unroll
            for (int nt = 0; nt < 8; ++nt) {
                unsigned b0 = s_W[(kw+tig)*72 + nt*8 + g];
                unsigned b1 = s_W[(kw+tig+4)*72 + nt*8 + g];
                mma_tf32(acc[nt][0], acc[nt][1], acc[nt][2], acc[nt][3], a0, a1, a2, a3, b0, b1);
            }
        }
    }

    #pragma unroll
    for (int nt = 0; nt < 8; ++nt) {
        int col = nt*8 + 2*tig;
        float b0 = lin2_b[col], b1 = lin2_b[col+1];
        int r0 = rows0 + mr + g, r1 = r0 + 8;
        bool v0 = r0 < Nq, v1 = r1 < Nq;
        float2 a0r = v0 ? *(const float2*)(g_att + r0*64 + col) : make_float2(0.f, 0.f);
        float2 a1r = v1 ? *(const float2*)(g_att + r1*64 + col) : make_float2(0.f, 0.f);
        float x00 = acc[nt][0] + b0 + a0r.x, x01 = acc[nt][1] + b1 + a0r.y;
        float x10 = acc[nt][2] + b0 + a1r.x, x11 = acc[nt][3] + b1 + a1r.y;
        if (v0) { float2 o = {x00, x01}; *(float2*)(g_x + r0*64 + col) = o; }
        if (v1) { float2 o = {x10, x11}; *(float2*)(g_x + r1*64 + col) = o; }
        float m00 = v0 ? x00 : 0.f, m01 = v0 ? x01 : 0.f;
        float m10 = v1 ? x10 : 0.f, m11 = v1 ? x11 : 0.f;
        float se = m00 + m10,                 so = m01 + m11;
        float sq = m00*m00 + m10*m10,         qo = m01*m01 + m11*m11;
        #pragma unroll
        for (int o = 16; o >= 4; o >>= 1) {
            se += __shfl_down_sync(0xffffffffu, se, o);
            so += __shfl_down_sync(0xffffffffu, so, o);
            sq += __shfl_down_sync(0xffffffffu, sq, o);
            qo += __shfl_down_sync(0xffffffffu, qo, o);
        }
        if (lane < 4) {
            atomicAdd(&s_ps[col], se);  atomicAdd(&s_pq[col], sq);
            atomicAdd(&s_ps[col+1], so); atomicAdd(&s_pq[col+1], qo);
        }
    }
    __syncthreads();
    if (tid < 64) {
        atomicAdd(&g_sum1[tid], (double)s_ps[tid]);
        atomicAdd(&g_sq1[tid],  (double)s_pq[tid]);
    }
}

// ============================================================================
// proj: g_z = BN1(g_x) @ outl_w^T + outl_b, BN2 stats. Inlines BN1 finalize.
// ============================================================================
#define SM_P ((64 * 72 + 128 * PADK + 256) * 4)
__global__ __launch_bounds__(256) void proj_mma(
    const float* __restrict__ outl_b,
    const float* __restrict__ norm_g, const float* __restrict__ norm_b)
{
    extern __shared__ unsigned sm[];
    unsigned* s_W = sm;
    unsigned* s_A = sm + 64 * 72;
    float* s_ps = (float*)(s_A + 128 * PADK);
    float* s_pq = s_ps + 64;
    float* s_mu = s_pq + 64;
    float* s_rs = s_mu + 64;
    const int tid = threadIdx.x, lane = tid & 31, w = tid >> 5;
    const int g = lane >> 2, tig = lane & 3, mr = w * 16;
    const int rows0 = blockIdx.x * 128;

    if (tid < 64) {
        s_ps[tid] = 0.f; s_pq[tid] = 0.f;
        double m = g_sum1[tid] / (double)Nq;
        double v = g_sq1[tid] / (double)Nq - m * m;
        if (v < 0) v = 0;
        s_mu[tid] = (float)m;
        s_rs[tid] = (float)(1.0 / sqrt(v + 1e-5));
    }
    for (int i = tid; i < 1152; i += 256)
        ((uint4*)s_W)[i] = ((const uint4*)g_Wl)[i];
    __syncthreads();
    {
        const int c = tid & 63;
        const float mu = s_mu[c], rs = s_rs[c], ga = norm_g[c], be = norm_b[c];
        for (int i = tid; i < 128 * 64; i += 256) {
            int r = i >> 6, row = rows0 + r;
            float v = 0.f;
            if (row < Nq) v = (g_x[row * 64 + c] - mu) * rs * ga + be;
            s_A[r * PADK + c] = f2tf32(v);
        }
    }
    __syncthreads();

    float acc[8][4] = {};
    #pragma unroll
    for (int ks = 0; ks < 8; ++ks) {
        int k0 = ks * 8;
        unsigned a0 = s_A[(mr+g)*PADK + k0 + tig];
        unsigned a1 = s_A[(mr+g+8)*PADK + k0 + tig];
        unsigned a2 = s_A[(mr+g)*PADK + k0 + tig + 4];
        unsigned a3 = s_A[(mr+g+8)*PADK + k0 + tig + 4];
        #pragma unroll
        for (int nt = 0; nt < 8; ++nt) {
            unsigned b0 = s_W[(k0+tig)*72 + nt*8 + g];
            unsigned b1 = s_W[(k0+tig+4)*72 + nt*8 + g];
            mma_tf32(acc[nt][0], acc[nt][1], acc[nt][2], acc[nt][3], a0, a1, a2, a3, b0, b1);
        }
    }
    #pragma unroll
    for (int nt = 0; nt < 8; ++nt) {
        int col = nt*8 + 2*tig;
        float b0 = outl_b[col], b1 = outl_b[col+1];
        int r0 = rows0 + mr + g, r1 = r0 + 8;
        bool v0 = r0 < Nq, v1 = r1 < Nq;
        float x00 = acc[nt][0] + b0, x01 = acc[nt][1] + b1;
        float x10 = acc[nt][2] + b0, x11 = acc[nt][3] + b1;
        if (v0) { float2 o = {x00, x01}; *(float2*)(g_z + r0*64 + col) = o; }
        if (v1) { float2 o = {x10, x11}; *(float2*)(g_z + r1*64 + col) = o; }
        float m00 = v0 ? x00 : 0.f, m01 = v0 ? x01 : 0.f;
        float m10 = v1 ? x10 : 0.f, m11 = v1 ? x11 : 0.f;
        float se = m00 + m10,                 so = m01 + m11;
        float sq = m00*m00 + m10*m10,         qo = m01*m01 + m11*m11;
        #pragma unroll
        for (int o = 16; o >= 4; o >>= 1) {
            se += __shfl_down_sync(0xffffffffu, se, o);
            so += __shfl_down_sync(0xffffffffu, so, o);
            sq += __shfl_down_sync(0xffffffffu, sq, o);
            qo += __shfl_down_sync(0xffffffffu, qo, o);
        }
        if (lane < 4) {
            atomicAdd(&s_ps[col], se);  atomicAdd(&s_pq[col], sq);
            atomicAdd(&s_ps[col+1], so); atomicAdd(&s_pq[col+1], qo);
        }
    }
    __syncthreads();
    if (tid < 64) {
        atomicAdd(&g_sum2[tid], (double)s_ps[tid]);
        atomicAdd(&g_sq2[tid],  (double)s_pq[tid]);
    }
}

// ============================================================================
// final: BN2 + relu -> out. Inlines BN2 finalize per block.
// ============================================================================
__global__ void final_kernel(float* __restrict__ out,
                             const float* __restrict__ obn_g,
                             const float* __restrict__ obn_b)
{
    __shared__ float s_mu[64], s_rs[64];
    const int tid = threadIdx.x;
    if (tid < 64) {
        double m = g_sum2[tid] / (double)Nq;
        double v = g_sq2[tid] / (double)Nq - m * m;
        if (v < 0) v = 0;
        s_mu[tid] = (float)m;
        s_rs[tid] = (float)(1.0 / sqrt(v + 1e-5));
    }
    __syncthreads();
    int i = blockIdx.x * 256 + tid;
    if (i < Nq * 64) {
        int o = i & 63;
        float v = (g_z[i] - s_mu[o]) * s_rs[o] * obn_g[o] + obn_b[o];
        out[i] = fmaxf(v, 0.f);
    }
}

extern "C" void kernel_launch(void* const* d_in, const int* in_sizes, int n_in,
                              void* d_out, int out_size) {
    const float* vf     = (const float*)d_in[0];
    const float* vc     = (const float*)d_in[1];
    const float* qcoord = (const float*)d_in[2];
    const int*   kidx   = (const int*)  d_in[3];
    const float* q_w    = (const float*)d_in[4];
    const float* q_b    = (const float*)d_in[5];
    const float* kpos_w = (const float*)d_in[6];
    const float* kpos_b = (const float*)d_in[7];
    const float* in_w   = (const float*)d_in[8];
    const float* in_b   = (const float*)d_in[9];
    const float* out_w  = (const float*)d_in[10];
    const float* out_b  = (const float*)d_in[11];
    const float* lin1_w = (const float*)d_in[12];
    const float* lin1_b = (const float*)d_in[13];
    const float* lin2_w = (const float*)d_in[14];
    const float* lin2_b = (const float*)d_in[15];
    const float* norm_g = (const float*)d_in[16];
    const float* norm_b = (const float*)d_in[17];
    const float* outl_w = (const float*)d_in[18];
    const float* outl_b = (const float*)d_in[19];
    const float* obn_g  = (const float*)d_in[20];
    const float* obn_b  = (const float*)d_in[21];
    float* out = (float*)d_out;

    cudaFuncSetAttribute(attn_kernel, cudaFuncAttributeMaxDynamicSharedMemorySize, SMEM_ATTN);
    cudaFuncSetAttribute(qproj_mma,   cudaFuncAttributeMaxDynamicSharedMemorySize, SM_Q);
    cudaFuncSetAttribute(ffn1_mma,    cudaFuncAttributeMaxDynamicSharedMemorySize, SM_F1);
    cudaFuncSetAttribute(ffn2_mma,    cudaFuncAttributeMaxDynamicSharedMemorySize, SM_F2);
    cudaFuncSetAttribute(ffn3_mma,    cudaFuncAttributeMaxDynamicSharedMemorySize, SM_F3);
    cudaFuncSetAttribute(proj_mma,    cudaFuncAttributeMaxDynamicSharedMemorySize, SM_P);

    int smCount = 148;
    cudaDeviceGetAttribute(&smCount, cudaDevAttrMultiProcessorCount, 0);
    const int attnGrid = 2 * smCount;   // persistent, 2 CTAs/SM
    const int RB = (Nq + 127) / 128;    // 157

    prep_kernel<<<13, 256>>>(in_w, out_w, lin1_w, lin2_w, outl_w);   // launch 1
    zero_stats<<<1, 64>>>();                                         // launch 2
    qproj_mma<<<RB, 256, SM_Q>>>(qcoord, q_w, q_b, in_b);            // launch 3
    attn_kernel<<<attnGrid, 384, SMEM_ATTN>>>(vf, vc, qcoord, kidx,
                                              kpos_w, kpos_b, in_b); // launch 4 (ncu)
    ffn1_mma<<<RB, 256, SM_F1>>>(out_b);
    ffn2_mma<<<(Nq + 63) / 64, 256, SM_F2>>>(lin1_b);
    ffn3_mma<<<RB, 256, SM_F3>>>(lin2_b);
    proj_mma<<<RB, 256, SM_P>>>(outl_b, norm_g, norm_b);
    final_kernel<<<(Nq * 64 + 255) / 256, 256>>>(out, obn_g, obn_b);
}

// round 14
// speedup vs baseline: 1.2741x; 1.2741x over previous
#include <cuda_runtime.h>
#include <math.h>

#define Nq   20000
#define KK   48
#define PADK 68
#define BST  140   // B2 ull row stride (conflict-free: 140 mod 16 = 12)

// ---- scratch ----
__device__ float  g_q[Nq * 64];
__device__ float  g_ctx[Nq * 64];
__device__ float  g_att[Nq * 64];
__device__ float  g_hid[Nq * 256];
__device__ float  g_x[Nq * 64];
__device__ float  g_z[Nq * 64];
__device__ double g_sum1[64], g_sq1[64];
__device__ double g_sum2[64], g_sq2[64];
// pre-converted tf32 weights (padded layouts)
__device__ unsigned long long g_B2d[32 * BST];
__device__ unsigned g_Wq[64 * 72];
__device__ unsigned g_Wo[64 * 72];
__device__ unsigned g_W1[64 * 264];
__device__ unsigned g_W2[256 * 72];
__device__ unsigned g_Wl[64 * 72];

__device__ __forceinline__ unsigned f2tf32(float x) {
    unsigned r; asm("cvt.rna.tf32.f32 %0, %1;" : "=r"(r) : "f"(x)); return r;
}
__device__ __forceinline__ void mma_tf32(float& d0, float& d1, float& d2, float& d3,
                                         unsigned a0, unsigned a1, unsigned a2, unsigned a3,
                                         unsigned b0, unsigned b1) {
    asm volatile("mma.sync.aligned.m16n8k8.row.col.f32.tf32.tf32.f32 "
                 "{%0,%1,%2,%3}, {%4,%5,%6,%7}, {%8,%9}, {%0,%1,%2,%3};"
                 : "+f"(d0), "+f"(d1), "+f"(d2), "+f"(d3)
                 : "r"(a0), "r"(a1), "r"(a2), "r"(a3), "r"(b0), "r"(b1));
}

// ============================================================================
// prep: convert weights to tf32 padded layouts (once per launch)
// ============================================================================
__global__ __launch_bounds__(256) void prep_kernel(
    const float* __restrict__ in_w,  const float* __restrict__ out_w,
    const float* __restrict__ lin1_w, const float* __restrict__ lin2_w,
    const float* __restrict__ outl_w)
{
    const int tid = threadIdx.x, b = blockIdx.x;
    if (b == 0) {
        for (int i = tid; i < 4096; i += 256) {
            int n = i >> 6, k = i & 63;
            g_Wq[k * 72 + n] = f2tf32(in_w[n * 64 + k]);
        }
    } else if (b <= 2) {             // B2: in_w rows 64..191 (K|V), packed pairs
        for (int i = (b - 1) * 4096 + tid; i < b * 4096; i += 256) {
            int n = i >> 6, k = i & 63;
            int ks = k >> 3, rem = k & 7, tg = rem & 3, slot = rem >> 2;
            ((unsigned*)g_B2d)[(((ks*4+tg)*BST) + n) * 2 + slot] = f2tf32(in_w[4096 + i]);
        }
    } else if (b == 3) {
        for (int i = tid; i < 4096; i += 256) {
            int n = i >> 6, k = i & 63;
            g_Wo[k * 72 + n] = f2tf32(out_w[n * 64 + k]);
        }
    } else if (b <= 7) {
        for (int i = (b - 4) * 4096 + tid; i < (b - 3) * 4096; i += 256) {
            int n = i >> 6, k = i & 63;
            g_W1[k * 264 + n] = f2tf32(lin1_w[n * 64 + k]);
        }
    } else if (b <= 11) {
        for (int i = (b - 8) * 4096 + tid; i < (b - 7) * 4096; i += 256) {
            int k = i >> 6, n = i & 63;
            g_W2[k * 72 + n] = f2tf32(lin2_w[n * 256 + k]);
        }
    } else {
        for (int i = tid; i < 4096; i += 256) {
            int n = i >> 6, k = i & 63;
            g_Wl[k * 72 + n] = f2tf32(outl_w[n * 64 + k]);
        }
    }
}

__global__ void zero_stats() {
    int t = threadIdx.x;
    if (t < 64) { g_sum1[t] = 0.0; g_sq1[t] = 0.0; g_sum2[t] = 0.0; g_sq2[t] = 0.0; }
}

// ============================================================================
// qproj
// ============================================================================
#define SM_Q ((64 * 72 + 128 * PADK) * 4)
__global__ __launch_bounds__(256) void qproj_mma(
    const float* __restrict__ qc, const float* __restrict__ q_w, const float* __restrict__ q_b,
    const float* __restrict__ in_b)
{
    extern __shared__ unsigned sm[];
    unsigned* s_W = sm;
    unsigned* s_A = sm + 64 * 72;
    const int tid = threadIdx.x, lane = tid & 31, w = tid >> 5;
    const int g = lane >> 2, tig = lane & 3, mr = w * 16;
    const int rows0 = blockIdx.x * 128;

    for (int i = tid; i < 1152; i += 256)
        ((uint4*)s_W)[i] = ((const uint4*)g_Wq)[i];
    {
        const int c = tid & 63;
        const float w0 = q_w[c*3], w1 = q_w[c*3+1], w2 = q_w[c*3+2], b = q_b[c];
        for (int i = tid; i < 128 * 64; i += 256) {
            int r = i >> 6, row = rows0 + r;
            float v = 0.f;
            if (row < Nq)
                v = fmaxf(b + w0*qc[row*3] + w1*qc[row*3+1] + w2*qc[row*3+2], 0.f);
            s_A[r * PADK + c] = f2tf32(v);
        }
    }
    __syncthreads();

    float acc[8][4] = {};
    #pragma unroll
    for (int ks = 0; ks < 8; ++ks) {
        int k0 = ks * 8;
        unsigned a0 = s_A[(mr+g)*PADK + k0 + tig];
        unsigned a1 = s_A[(mr+g+8)*PADK + k0 + tig];
        unsigned a2 = s_A[(mr+g)*PADK + k0 + tig + 4];
        unsigned a3 = s_A[(mr+g+8)*PADK + k0 + tig + 4];
        #pragma unroll
        for (int nt = 0; nt < 8; ++nt) {
            unsigned b0 = s_W[(k0+tig)*72 + nt*8 + g];
            unsigned b1 = s_W[(k0+tig+4)*72 + nt*8 + g];
            mma_tf32(acc[nt][0], acc[nt][1], acc[nt][2], acc[nt][3], a0, a1, a2, a3, b0, b1);
        }
    }
    #pragma unroll
    for (int nt = 0; nt < 8; ++nt) {
        int col = nt*8 + 2*tig;
        float b0 = in_b[col], b1 = in_b[col+1];
        int r0 = rows0 + mr + g, r1 = r0 + 8;
        if (r0 < Nq) { float2 o = {(acc[nt][0]+b0)*0.25f, (acc[nt][1]+b1)*0.25f};
                       *(float2*)(g_q + r0*64 + col) = o; }
        if (r1 < Nq) { float2 o = {(acc[nt][2]+b0)*0.25f, (acc[nt][3]+b1)*0.25f};
                       *(float2*)(g_q + r1*64 + col) = o; }
    }
}

// ============================================================================
// attention kernel: 4 queries/block, 384 threads (12 warps), N-split across
// warps (0-5 K half, 6-11 V half, M=32 rows each), 2 CTAs/SM.
// Gather fused into phase 1 (kidx/vc/qc read directly, warp-uniform).
// ============================================================================
// smem words: kf 192*68=13056 | B2 8960 | q 256 | sc 768 | idx 192
#define SMEM_ATTN ((13056 + 8960 + 256 + 768 + 192) * 4)
__global__ __launch_bounds__(384, 2) void attn_kernel(
    const float* __restrict__ vf,     const float* __restrict__ vc,
    const float* __restrict__ qc,     const int*   __restrict__ kidx,
    const float* __restrict__ kpos_w, const float* __restrict__ kpos_b,
    const float* __restrict__ in_b)
{
    extern __shared__ unsigned smu[];
    unsigned* s_kfu = smu;                         // [192][68] tf32 A (alias vp float)
    unsigned* s_B2  = smu + 192 * PADK;            // ull[32][140] = 8960 words
    float*    s_q   = (float*)(s_B2 + 8960);       // 256
    float*    s_sc  = s_q + 256;                   // 768
    int*      s_idx = (int*)(s_sc + 768);          // 192

    const int tid  = threadIdx.x;
    const int lane = tid & 31;
    const int w    = tid >> 5;            // 0..11
    const int n0   = blockIdx.x * 4;

    // ---- phase 1: B2 copy + idx + q stage + gather (one barrier total) ----
    for (int i = tid; i < 2240; i += 384)
        ((uint4*)s_B2)[i] = ((const uint4*)g_B2d)[i];
    if (tid < 192) s_idx[tid] = kidx[n0 * KK + tid];
    if (tid < 256) s_q[tid] = g_q[(n0 + (tid >> 6)) * 64 + (tid & 63)];
    {
        const int c2 = (tid & 31) * 2;
        const float ka0 = kpos_w[c2*3],   ka1 = kpos_w[c2*3+1], ka2 = kpos_w[c2*3+2];
        const float kb0 = kpos_w[c2*3+3], kb1 = kpos_w[c2*3+4], kb2 = kpos_w[c2*3+5];
        const float kba = kpos_b[c2], kbb = kpos_b[c2+1];
        for (int e = tid; e < 192 * 32; e += 384) {
            int kg = e >> 5;                        // warp-uniform
            int n  = n0 + kg / KK;
            int idx = kidx[n0 * KK + kg];           // == kidx[n*KK + kg%KK], warp-uniform
            int safe = idx < 0 ? 0 : idx;
            float r0 = vc[safe*3+0] - qc[n*3+0];
            float r1 = vc[safe*3+1] - qc[n*3+1];
            float r2 = vc[safe*3+2] - qc[n*3+2];
            float2 f = *(const float2*)(vf + safe * 64 + c2);
            float p0 = kba + ka0*r0 + ka1*r1 + ka2*r2;
            float p1 = kbb + kb0*r0 + kb1*r1 + kb2*r2;
            uint2 o = { f2tf32(f.x + fmaxf(p0, 0.f)), f2tf32(f.y + fmaxf(p1, 0.f)) };
            *(uint2*)(s_kfu + kg * PADK + c2) = o;
        }
    }
    __syncthreads();

    const int g    = lane >> 2;
    const int tig  = lane & 3;
    const int half = (w >= 6);
    const int mw   = w - half * 6;
    const int mr   = mw * 32;
    const int cb   = half * 64;
    const unsigned long long* B2u = (const unsigned long long*)s_B2;

    float acc0[8][4], acc1[8][4];
    #pragma unroll
    for (int nt = 0; nt < 8; ++nt) {
        int cc = 8*nt + 2*tig;
        float b0 = in_b[64 + cb + cc], b1 = in_b[64 + cb + cc + 1];
        acc0[nt][0] = b0; acc0[nt][1] = b1; acc0[nt][2] = b0; acc0[nt][3] = b1;
        acc1[nt][0] = b0; acc1[nt][1] = b1; acc1[nt][2] = b0; acc1[nt][3] = b1;
    }
    #pragma unroll
    for (int ks = 0; ks < 8; ++ks) {
        const int k0 = ks * 8;
        unsigned a00 = s_kfu[(mr+g)*PADK + k0 + tig];
        unsigned a01 = s_kfu[(mr+g+8)*PADK + k0 + tig];
        unsigned a02 = s_kfu[(mr+g)*PADK + k0 + tig + 4];
        unsigned a03 = s_kfu[(mr+g+8)*PADK + k0 + tig + 4];
        unsigned a10 = s_kfu[(mr+g+16)*PADK + k0 + tig];
        unsigned a11 = s_kfu[(mr+g+24)*PADK + k0 + tig];
        unsigned a12 = s_kfu[(mr+g+16)*PADK + k0 + tig + 4];
        unsigned a13 = s_kfu[(mr+g+24)*PADK + k0 + tig + 4];
        const unsigned long long* bp = B2u + (ks*4 + tig) * BST + g + cb;
        #pragma unroll
        for (int nt = 0; nt < 8; ++nt) {
            unsigned long long pv = bp[nt * 8];
            unsigned b0 = (unsigned)pv, b1 = (unsigned)(pv >> 32);
            mma_tf32(acc0[nt][0], acc0[nt][1], acc0[nt][2], acc0[nt][3],
                     a00, a01, a02, a03, b0, b1);
            mma_tf32(acc1[nt][0], acc1[nt][1], acc1[nt][2], acc1[nt][3],
                     a10, a11, a12, a13, b0, b1);
        }
    }
    __syncthreads();   // all A reads complete before vp aliases kf

    if (half == 0) {
        #pragma unroll
        for (int t = 0; t < 2; ++t) {
            int r1 = mr + 16*t + g, r2 = r1 + 8;
            int q1 = r1 / KK, kk1 = r1 - q1 * KK;
            int q2 = r2 / KK, kk2 = r2 - q2 * KK;
            #pragma unroll
            for (int h = 0; h < 4; ++h) {
                int nA = 2*h, nB = 2*h + 1;
                int cA = 8*nA + 2*tig, cB = 8*nB + 2*tig;
                float qA0 = s_q[q1*64+cA], qA1 = s_q[q1*64+cA+1];
                float qB0 = s_q[q1*64+cB], qB1 = s_q[q1*64+cB+1];
                float qC0 = s_q[q2*64+cA], qC1 = s_q[q2*64+cA+1];
                float qD0 = s_q[q2*64+cB], qD1 = s_q[q2*64+cB+1];
                float s0, s1;
                if (t == 0) {
                    s0 = acc0[nA][0]*qA0 + acc0[nA][1]*qA1 + acc0[nB][0]*qB0 + acc0[nB][1]*qB1;
                    s1 = acc0[nA][2]*qC0 + acc0[nA][3]*qC1 + acc0[nB][2]*qD0 + acc0[nB][3]*qD1;
                } else {
                    s0 = acc1[nA][0]*qA0 + acc1[nA][1]*qA1 + acc1[nB][0]*qB0 + acc1[nB][1]*qB1;
                    s1 = acc1[nA][2]*qC0 + acc1[nA][3]*qC1 + acc1[nB][2]*qD0 + acc1[nB][3]*qD1;
                }
                s0 += __shfl_xor_sync(0xffffffffu, s0, 1);
                s0 += __shfl_xor_sync(0xffffffffu, s0, 2);
                s1 += __shfl_xor_sync(0xffffffffu, s1, 1);
                s1 += __shfl_xor_sync(0xffffffffu, s1, 2);
                if (tig == 0) {
                    s_sc[(q1*4+h)*48 + kk1] = (s_idx[r1] < 0) ? -1e30f : s0;
                    s_sc[(q2*4+h)*48 + kk2] = (s_idx[r2] < 0) ? -1e30f : s1;
                }
            }
        }
    } else {
        float* s_vp = (float*)s_kfu;
        #pragma unroll
        for (int t = 0; t < 2; ++t) {
            int r1 = mr + 16*t + g, r2 = r1 + 8;
            #pragma unroll
            for (int nt = 0; nt < 8; ++nt) {
                int cc = 8*nt + 2*tig;
                float2 o1, o2;
                if (t == 0) { o1 = make_float2(acc0[nt][0], acc0[nt][1]);
                              o2 = make_float2(acc0[nt][2], acc0[nt][3]); }
                else        { o1 = make_float2(acc1[nt][0], acc1[nt][1]);
                              o2 = make_float2(acc1[nt][2], acc1[nt][3]); }
                *(float2*)(s_vp + r1*PADK + cc) = o1;
                *(float2*)(s_vp + r2*PADK + cc) = o2;
            }
        }
    }
    __syncthreads();

    // ---- softmax (16 (q,h) rows over 12 warps) ----
    for (int r = w; r < 16; r += 12) {
        float* sc = s_sc + r * 48;
        float v0 = sc[lane];
        float v1 = (lane < 16) ? sc[32 + lane] : -1e30f;
        float m = fmaxf(v0, v1);
        #pragma unroll
        for (int o = 16; o > 0; o >>= 1) m = fmaxf(m, __shfl_xor_sync(0xffffffffu, m, o));
        float e0 = __expf(v0 - m);
        float e1 = (lane < 16) ? __expf(v1 - m) : 0.f;
        float s = e0 + e1;
        #pragma unroll
        for (int o = 16; o > 0; o >>= 1) s += __shfl_xor_sync(0xffffffffu, s, o);
        float inv = 1.f / s;
        sc[lane] = e0 * inv;
        if (lane < 16) sc[32 + lane] = e1 * inv;
    }
    __syncthreads();

    // ---- ctx = attn @ V -> g_ctx ----
    {
        const float* s_vp = (const float*)s_kfu;
        if (tid < 256) {
            int q = tid >> 6, c = tid & 63, h = c >> 4;
            const float* a  = s_sc + (q * 4 + h) * 48;
            const float* vp = s_vp + (q * 48) * PADK + c;
            float acc2 = 0.f;
            #pragma unroll 8
            for (int kk = 0; kk < KK; ++kk) acc2 = fmaf(a[kk], vp[kk * PADK], acc2);
            g_ctx[(n0 + q) * 64 + c] = acc2;
        }
    }
}

// ============================================================================
// ffn1: g_att = g_ctx @ out_w^T + out_b
// ============================================================================
#define SM_F1 ((64 * 72 + 128 * PADK) * 4)
__global__ __launch_bounds__(256) void ffn1_mma(const float* __restrict__ out_b)
{
    extern __shared__ unsigned sm[];
    unsigned* s_W = sm;
    unsigned* s_A = sm + 64 * 72;
    const int tid = threadIdx.x, lane = tid & 31, w = tid >> 5;
    const int g = lane >> 2, tig = lane & 3, mr = w * 16;
    const int rows0 = blockIdx.x * 128;

    for (int i = tid; i < 1152; i += 256)
        ((uint4*)s_W)[i] = ((const uint4*)g_Wo)[i];
    for (int i = tid; i < 128 * 64; i += 256) {
        int r = i >> 6, c = i & 63, row = rows0 + r;
        s_A[r * PADK + c] = f2tf32(row < Nq ? g_ctx[row * 64 + c] : 0.f);
    }
    __syncthreads();

    float acc[8][4] = {};
    #pragma unroll
    for (int ks = 0; ks < 8; ++ks) {
        int k0 = ks * 8;
        unsigned a0 = s_A[(mr+g)*PADK + k0 + tig];
        unsigned a1 = s_A[(mr+g+8)*PADK + k0 + tig];
        unsigned a2 = s_A[(mr+g)*PADK + k0 + tig + 4];
        unsigned a3 = s_A[(mr+g+8)*PADK + k0 + tig + 4];
        #pragma unroll
        for (int nt = 0; nt < 8; ++nt) {
            unsigned b0 = s_W[(k0+tig)*72 + nt*8 + g];
            unsigned b1 = s_W[(k0+tig+4)*72 + nt*8 + g];
            mma_tf32(acc[nt][0], acc[nt][1], acc[nt][2], acc[nt][3], a0, a1, a2, a3, b0, b1);
        }
    }
    #pragma unroll
    for (int nt = 0; nt < 8; ++nt) {
        int col = nt*8 + 2*tig;
        float b0 = out_b[col], b1 = out_b[col+1];
        int r0 = rows0 + mr + g, r1 = r0 + 8;
        if (r0 < Nq) { float2 o = {acc[nt][0]+b0, acc[nt][1]+b1};
                       *(float2*)(g_att + r0*64 + col) = o; }
        if (r1 < Nq) { float2 o = {acc[nt][2]+b0, acc[nt][3]+b1};
                       *(float2*)(g_att + r1*64 + col) = o; }
    }
}

// ============================================================================
// ffn2: g_hid = relu(g_att @ lin1_w^T + lin1_b)
// ============================================================================
#define SM_F2 ((64 * 264 + 64 * PADK) * 4)
__global__ __launch_bounds__(256) void ffn2_mma(const float* __restrict__ lin1_b)
{
    extern __shared__ unsigned sm[];
    unsigned* s_W = sm;              // [64][264]
    unsigned* s_A = sm + 64 * 264;   // [64][68]
    const int tid = threadIdx.x, lane = tid & 31, w = tid >> 5;
    const int g = lane >> 2, tig = lane & 3;
    const int mr = (w & 3) * 16, nbase = (w >> 2) * 128;
    const int rows0 = blockIdx.x * 64;

    for (int i = tid; i < 4224; i += 256)
        ((uint4*)s_W)[i] = ((const uint4*)g_W1)[i];
    for (int i = tid; i < 64 * 64; i += 256) {
        int r = i >> 6, c = i & 63, row = rows0 + r;
        s_A[r * PADK + c] = f2tf32(row < Nq ? g_att[row * 64 + c] : 0.f);
    }
    __syncthreads();

    float acc[16][4];
    #pragma unroll
    for (int nt = 0; nt < 16; ++nt)
        #pragma unroll
        for (int j = 0; j < 4; ++j) acc[nt][j] = 0.f;

    #pragma unroll
    for (int ks = 0; ks < 8; ++ks) {
        int k0 = ks * 8;
        unsigned a0 = s_A[(mr+g)*PADK + k0 + tig];
        unsigned a1 = s_A[(mr+g+8)*PADK + k0 + tig];
        unsigned a2 = s_A[(mr+g)*PADK + k0 + tig + 4];
        unsigned a3 = s_A[(mr+g+8)*PADK + k0 + tig + 4];
        #pragma unroll
        for (int nt = 0; nt < 16; ++nt) {
            unsigned b0 = s_W[(k0+tig)*264 + nbase + nt*8 + g];
            unsigned b1 = s_W[(k0+tig+4)*264 + nbase + nt*8 + g];
            mma_tf32(acc[nt][0], acc[nt][1], acc[nt][2], acc[nt][3], a0, a1, a2, a3, b0, b1);
        }
    }
    #pragma unroll
    for (int nt = 0; nt < 16; ++nt) {
        int col = nbase + nt*8 + 2*tig;
        float b0 = lin1_b[col], b1 = lin1_b[col+1];
        int r0 = rows0 + mr + g, r1 = r0 + 8;
        if (r0 < Nq) { float2 o = {fmaxf(acc[nt][0]+b0, 0.f), fmaxf(acc[nt][1]+b1, 0.f)};
                       *(float2*)(g_hid + r0*256 + col) = o; }
        if (r1 < Nq) { float2 o = {fmaxf(acc[nt][2]+b0, 0.f), fmaxf(acc[nt][3]+b1, 0.f)};
                       *(float2*)(g_hid + r1*256 + col) = o; }
    }
}

// ============================================================================
// ffn3: g_x = g_att + g_hid @ lin2_w^T + lin2_b, BN1 stats
// ============================================================================
#define SM_F3 ((256 * 72 + 128 * PADK + 128) * 4)
__global__ __launch_bounds__(256) void ffn3_mma(const float* __restrict__ lin2_b)
{
    extern __shared__ unsigned sm[];
    unsigned* s_W = sm;               // [256][72]
    unsigned* s_A = sm + 256 * 72;    // [128][68]
    float* s_ps = (float*)(s_A + 128 * PADK);
    float* s_pq = s_ps + 64;
    const int tid = threadIdx.x, lane = tid & 31, w = tid >> 5;
    const int g = lane >> 2, tig = lane & 3, mr = w * 16;
    const int rows0 = blockIdx.x * 128;

    if (tid < 64) { s_ps[tid] = 0.f; s_pq[tid] = 0.f; }
    for (int i = tid; i < 4608; i += 256)
        ((uint4*)s_W)[i] = ((const uint4*)g_W2)[i];

    float acc[8][4] = {};
    for (int kc = 0; kc < 4; ++kc) {
        __syncthreads();
        for (int i = tid; i < 128 * 64; i += 256) {
            int r = i >> 6, c = i & 63, row = rows0 + r;
            s_A[r * PADK + c] = f2tf32(row < Nq ? g_hid[row * 256 + kc * 64 + c] : 0.f);
        }
        __syncthreads();
        #pragma unroll
        for (int ks = 0; ks < 8; ++ks) {
            int k0 = ks * 8;
            unsigned a0 = s_A[(mr+g)*PADK + k0 + tig];
            unsigned a1 = s_A[(mr+g+8)*PADK + k0 + tig];
            unsigned a2 = s_A[(mr+g)*PADK + k0 + tig + 4];
            unsigned a3 = s_A[(mr+g+8)*PADK + k0 + tig + 4];
            int kw = kc * 64 + k0;
            #pragma unroll
            for (int nt = 0; nt < 8; ++nt) {
                unsigned b0 = s_W[(kw+tig)*72 + nt*8 + g];
                unsigned b1 = s_W[(kw+tig+4)*72 + nt*8 + g];
                mma_tf32(acc[nt][0], acc[nt][1], acc[nt][2], acc[nt][3], a0, a1, a2, a3, b0, b1);
            }
        }
    }

    #pragma unroll
    for (int nt = 0; nt < 8; ++nt) {
        int col = nt*8 + 2*tig;
        float b0 = lin2_b[col], b1 = lin2_b[col+1];
        int r0 = rows0 + mr + g, r1 = r0 + 8;
        bool v0 = r0 < Nq, v1 = r1 < Nq;
        float2 a0r = v0 ? *(const float2*)(g_att + r0*64 + col) : make_float2(0.f, 0.f);
        float2 a1r = v1 ? *(const float2*)(g_att + r1*64 + col) : make_float2(0.f, 0.f);
        float x00 = acc[nt][0] + b0 + a0r.x, x01 = acc[nt][1] + b1 + a0r.y;
        float x10 = acc[nt][2] + b0 + a1r.x, x11 = acc[nt][3] + b1 + a1r.y;
        if (v0) { float2 o = {x00, x01}; *(float2*)(g_x + r0*64 + col) = o; }
        if (v1) { float2 o = {x10, x11}; *(float2*)(g_x + r1*64 + col) = o; }
        float m00 = v0 ? x00 : 0.f, m01 = v0 ? x01 : 0.f;
        float m10 = v1 ? x10 : 0.f, m11 = v1 ? x11 : 0.f;
        float se = m00 + m10,                 so = m01 + m11;
        float sq = m00*m00 + m10*m10,         qo = m01*m01 + m11*m11;
        #pragma unroll
        for (int o = 16; o >= 4; o >>= 1) {
            se += __shfl_down_sync(0xffffffffu, se, o);
            so += __shfl_down_sync(0xffffffffu, so, o);
            sq += __shfl_down_sync(0xffffffffu, sq, o);
            qo += __shfl_down_sync(0xffffffffu, qo, o);
        }
        if (lane < 4) {
            atomicAdd(&s_ps[col], se);  atomicAdd(&s_pq[col], sq);
            atomicAdd(&s_ps[col+1], so); atomicAdd(&s_pq[col+1], qo);
        }
    }
    __syncthreads();
    if (tid < 64) {
        atomicAdd(&g_sum1[tid], (double)s_ps[tid]);
        atomicAdd(&g_sq1[tid],  (double)s_pq[tid]);
    }
}

// ============================================================================
// proj: g_z = BN1(g_x) @ outl_w^T + outl_b, BN2 stats. Inlines BN1 finalize.
// ============================================================================
#define SM_P ((64 * 72 + 128 * PADK + 256) * 4)
__global__ __launch_bounds__(256) void proj_mma(
    const float* __restrict__ outl_b,
    const float* __restrict__ norm_g, const float* __restrict__ norm_b)
{
    extern __shared__ unsigned sm[];
    unsigned* s_W = sm;
    unsigned* s_A = sm + 64 * 72;
    float* s_ps = (float*)(s_A + 128 * PADK);
    float* s_pq = s_ps + 64;
    float* s_mu = s_pq + 64;
    float* s_rs = s_mu + 64;
    const int tid = threadIdx.x, lane = tid & 31, w = tid >> 5;
    const int g = lane >> 2, tig = lane & 3, mr = w * 16;
    const int rows0 = blockIdx.x * 128;

    if (tid < 64) {
        s_ps[tid] = 0.f; s_pq[tid] = 0.f;
        double m = g_sum1[tid] / (double)Nq;
        double v = g_sq1[tid] / (double)Nq - m * m;
        if (v < 0) v = 0;
        s_mu[tid] = (float)m;
        s_rs[tid] = (float)(1.0 / sqrt(v + 1e-5));
    }
    for (int i = tid; i < 1152; i += 256)
        ((uint4*)s_W)[i] = ((const uint4*)g_Wl)[i];
    __syncthreads();
    {
        const int c = tid & 63;
        const float mu = s_mu[c], rs = s_rs[c], ga = norm_g[c], be = norm_b[c];
        for (int i = tid; i < 128 * 64; i += 256) {
            int r = i >> 6, row = rows0 + r;
            float v = 0.f;
            if (row < Nq) v = (g_x[row * 64 + c] - mu) * rs * ga + be;
            s_A[r * PADK + c] = f2tf32(v);
        }
    }
    __syncthreads();

    float acc[8][4] = {};
    #pragma unroll
    for (int ks = 0; ks < 8; ++ks) {
        int k0 = ks * 8;
        unsigned a0 = s_A[(mr+g)*PADK + k0 + tig];
        unsigned a1 = s_A[(mr+g+8)*PADK + k0 + tig];
        unsigned a2 = s_A[(mr+g)*PADK + k0 + tig + 4];
        unsigned a3 = s_A[(mr+g+8)*PADK + k0 + tig + 4];
        #pragma unroll
        for (int nt = 0; nt < 8; ++nt) {
            unsigned b0 = s_W[(k0+tig)*72 + nt*8 + g];
            unsigned b1 = s_W[(k0+tig+4)*72 + nt*8 + g];
            mma_tf32(acc[nt][0], acc[nt][1], acc[nt][2], acc[nt][3], a0, a1, a2, a3, b0, b1);
        }
    }
    #pragma unroll
    for (int nt = 0; nt < 8; ++nt) {
        int col = nt*8 + 2*tig;
        float b0 = outl_b[col], b1 = outl_b[col+1];
        int r0 = rows0 + mr + g, r1 = r0 + 8;
        bool v0 = r0 < Nq, v1 = r1 < Nq;
        float x00 = acc[nt][0] + b0, x01 = acc[nt][1] + b1;
        float x10 = acc[nt][2] + b0, x11 = acc[nt][3] + b1;
        if (v0) { float2 o = {x00, x01}; *(float2*)(g_z + r0*64 + col) = o; }
        if (v1) { float2 o = {x10, x11}; *(float2*)(g_z + r1*64 + col) = o; }
        float m00 = v0 ? x00 : 0.f, m01 = v0 ? x01 : 0.f;
        float m10 = v1 ? x10 : 0.f, m11 = v1 ? x11 : 0.f;
        float se = m00 + m10,                 so = m01 + m11;
        float sq = m00*m00 + m10*m10,         qo = m01*m01 + m11*m11;
        #pragma unroll
        for (int o = 16; o >= 4; o >>= 1) {
            se += __shfl_down_sync(0xffffffffu, se, o);
            so += __shfl_down_sync(0xffffffffu, so, o);
            sq += __shfl_down_sync(0xffffffffu, sq, o);
            qo += __shfl_down_sync(0xffffffffu, qo, o);
        }
        if (lane < 4) {
            atomicAdd(&s_ps[col], se);  atomicAdd(&s_pq[col], sq);
            atomicAdd(&s_ps[col+1], so); atomicAdd(&s_pq[col+1], qo);
        }
    }
    __syncthreads();
    if (tid < 64) {
        atomicAdd(&g_sum2[tid], (double)s_ps[tid]);
        atomicAdd(&g_sq2[tid],  (double)s_pq[tid]);
    }
}

// ============================================================================
// final: BN2 + relu -> out. Inlines BN2 finalize per block.
// ============================================================================
__global__ void final_kernel(float* __restrict__ out,
                             const float* __restrict__ obn_g,
                             const float* __restrict__ obn_b)
{
    __shared__ float s_mu[64], s_rs[64];
    const int tid = threadIdx.x;
    if (tid < 64) {
        double m = g_sum2[tid] / (double)Nq;
        double v = g_sq2[tid] / (double)Nq - m * m;
        if (v < 0) v = 0;
        s_mu[tid] = (float)m;
        s_rs[tid] = (float)(1.0 / sqrt(v + 1e-5));
    }
    __syncthreads();
    int i = blockIdx.x * 256 + tid;
    if (i < Nq * 64) {
        int o = i & 63;
        float v = (g_z[i] - s_mu[o]) * s_rs[o] * obn_g[o] + obn_b[o];
        out[i] = fmaxf(v, 0.f);
    }
}

extern "C" void kernel_launch(void* const* d_in, const int* in_sizes, int n_in,
                              void* d_out, int out_size) {
    const float* vf     = (const float*)d_in[0];
    const float* vc     = (const float*)d_in[1];
    const float* qcoord = (const float*)d_in[2];
    const int*   kidx   = (const int*)  d_in[3];
    const float* q_w    = (const float*)d_in[4];
    const float* q_b    = (const float*)d_in[5];
    const float* kpos_w = (const float*)d_in[6];
    const float* kpos_b = (const float*)d_in[7];
    const float* in_w   = (const float*)d_in[8];
    const float* in_b   = (const float*)d_in[9];
    const float* out_w  = (const float*)d_in[10];
    const float* out_b  = (const float*)d_in[11];
    const float* lin1_w = (const float*)d_in[12];
    const float* lin1_b = (const float*)d_in[13];
    const float* lin2_w = (const float*)d_in[14];
    const float* lin2_b = (const float*)d_in[15];
    const float* norm_g = (const float*)d_in[16];
    const float* norm_b = (const float*)d_in[17];
    const float* outl_w = (const float*)d_in[18];
    const float* outl_b = (const float*)d_in[19];
    const float* obn_g  = (const float*)d_in[20];
    const float* obn_b  = (const float*)d_in[21];
    float* out = (float*)d_out;

    cudaFuncSetAttribute(attn_kernel, cudaFuncAttributeMaxDynamicSharedMemorySize, SMEM_ATTN);
    cudaFuncSetAttribute(qproj_mma,   cudaFuncAttributeMaxDynamicSharedMemorySize, SM_Q);
    cudaFuncSetAttribute(ffn1_mma,    cudaFuncAttributeMaxDynamicSharedMemorySize, SM_F1);
    cudaFuncSetAttribute(ffn2_mma,    cudaFuncAttributeMaxDynamicSharedMemorySize, SM_F2);
    cudaFuncSetAttribute(ffn3_mma,    cudaFuncAttributeMaxDynamicSharedMemorySize, SM_F3);
    cudaFuncSetAttribute(proj_mma,    cudaFuncAttributeMaxDynamicSharedMemorySize, SM_P);

    const int RB = (Nq + 127) / 128;    // 157

    prep_kernel<<<13, 256>>>(in_w, out_w, lin1_w, lin2_w, outl_w);   // launch 1
    zero_stats<<<1, 64>>>();                                         // launch 2
    qproj_mma<<<RB, 256, SM_Q>>>(qcoord, q_w, q_b, in_b);            // launch 3
    attn_kernel<<<Nq / 4, 384, SMEM_ATTN>>>(vf, vc, qcoord, kidx,
                                            kpos_w, kpos_b, in_b);   // launch 4 (ncu)
    ffn1_mma<<<RB, 256, SM_F1>>>(out_b);
    ffn2_mma<<<(Nq + 63) / 64, 256, SM_F2>>>(lin1_b);
    ffn3_mma<<<RB, 256, SM_F3>>>(lin2_b);
    proj_mma<<<RB, 256, SM_P>>>(outl_b, norm_g, norm_b);
    final_kernel<<<(Nq * 64 + 255) / 256, 256>>>(out, obn_g, obn_b);
}

// round 15
// speedup vs baseline: 1.3415x; 1.0529x over previous
#include <cuda_runtime.h>
#include <math.h>

#define Nq   20000
#define KK   48
#define PADK 68
#define BST  140   // B2 ull row stride (conflict-free: 140 mod 16 = 12)

// ---- scratch ----
__device__ float  g_q[Nq * 64];
__device__ float  g_ctx[Nq * 64];
__device__ float  g_att[Nq * 64];
__device__ float  g_hid[Nq * 256];
__device__ float  g_x[Nq * 64];
__device__ float  g_z[Nq * 64];
__device__ double g_sum1[64], g_sq1[64];
__device__ double g_sum2[64], g_sq2[64];
__device__ float  g_mu2[64], g_rs2[64];
// pre-converted tf32 weights (padded layouts)
__device__ unsigned long long g_B2d[32 * BST];
__device__ unsigned g_Wq[64 * 72];
__device__ unsigned g_Wo[64 * 72];
__device__ unsigned g_W1[64 * 264];
__device__ unsigned g_W2[256 * 72];
__device__ unsigned g_Wl[64 * 72];

__device__ __forceinline__ unsigned f2tf32(float x) {
    unsigned r; asm("cvt.rna.tf32.f32 %0, %1;" : "=r"(r) : "f"(x)); return r;
}
__device__ __forceinline__ void mma_tf32(float& d0, float& d1, float& d2, float& d3,
                                         unsigned a0, unsigned a1, unsigned a2, unsigned a3,
                                         unsigned b0, unsigned b1) {
    asm volatile("mma.sync.aligned.m16n8k8.row.col.f32.tf32.tf32.f32 "
                 "{%0,%1,%2,%3}, {%4,%5,%6,%7}, {%8,%9}, {%0,%1,%2,%3};"
                 : "+f"(d0), "+f"(d1), "+f"(d2), "+f"(d3)
                 : "r"(a0), "r"(a1), "r"(a2), "r"(a3), "r"(b0), "r"(b1));
}

// ============================================================================
// prep: convert weights to tf32 padded layouts (once per launch)
// ============================================================================
__global__ __launch_bounds__(256) void prep_kernel(
    const float* __restrict__ in_w,  const float* __restrict__ out_w,
    const float* __restrict__ lin1_w, const float* __restrict__ lin2_w,
    const float* __restrict__ outl_w)
{
    const int tid = threadIdx.x, b = blockIdx.x;
    if (b == 0) {
        for (int i = tid; i < 4096; i += 256) {
            int n = i >> 6, k = i & 63;
            g_Wq[k * 72 + n] = f2tf32(in_w[n * 64 + k]);
        }
    } else if (b <= 2) {             // B2: in_w rows 64..191 (K|V), packed pairs
        for (int i = (b - 1) * 4096 + tid; i < b * 4096; i += 256) {
            int n = i >> 6, k = i & 63;
            int ks = k >> 3, rem = k & 7, tg = rem & 3, slot = rem >> 2;
            ((unsigned*)g_B2d)[(((ks*4+tg)*BST) + n) * 2 + slot] = f2tf32(in_w[4096 + i]);
        }
    } else if (b == 3) {
        for (int i = tid; i < 4096; i += 256) {
            int n = i >> 6, k = i & 63;
            g_Wo[k * 72 + n] = f2tf32(out_w[n * 64 + k]);
        }
    } else if (b <= 7) {
        for (int i = (b - 4) * 4096 + tid; i < (b - 3) * 4096; i += 256) {
            int n = i >> 6, k = i & 63;
            g_W1[k * 264 + n] = f2tf32(lin1_w[n * 64 + k]);
        }
    } else if (b <= 11) {
        for (int i = (b - 8) * 4096 + tid; i < (b - 7) * 4096; i += 256) {
            int k = i >> 6, n = i & 63;
            g_W2[k * 72 + n] = f2tf32(lin2_w[n * 256 + k]);
        }
    } else {
        for (int i = tid; i < 4096; i += 256) {
            int n = i >> 6, k = i & 63;
            g_Wl[k * 72 + n] = f2tf32(outl_w[n * 64 + k]);
        }
    }
}

__global__ void zero_stats() {
    int t = threadIdx.x;
    if (t < 64) { g_sum1[t] = 0.0; g_sq1[t] = 0.0; g_sum2[t] = 0.0; g_sq2[t] = 0.0; }
}

// ============================================================================
// qproj
// ============================================================================
#define SM_Q ((64 * 72 + 128 * PADK) * 4)
__global__ __launch_bounds__(256) void qproj_mma(
    const float* __restrict__ qc, const float* __restrict__ q_w, const float* __restrict__ q_b,
    const float* __restrict__ in_b)
{
    extern __shared__ unsigned sm[];
    unsigned* s_W = sm;
    unsigned* s_A = sm + 64 * 72;
    const int tid = threadIdx.x, lane = tid & 31, w = tid >> 5;
    const int g = lane >> 2, tig = lane & 3, mr = w * 16;
    const int rows0 = blockIdx.x * 128;

    for (int i = tid; i < 1152; i += 256)
        ((uint4*)s_W)[i] = ((const uint4*)g_Wq)[i];
    {
        const int c = tid & 63;
        const float w0 = q_w[c*3], w1 = q_w[c*3+1], w2 = q_w[c*3+2], b = q_b[c];
        for (int i = tid; i < 128 * 64; i += 256) {
            int r = i >> 6, row = rows0 + r;
            float v = 0.f;
            if (row < Nq)
                v = fmaxf(b + w0*qc[row*3] + w1*qc[row*3+1] + w2*qc[row*3+2], 0.f);
            s_A[r * PADK + (i & 63)] = f2tf32(v);
        }
    }
    __syncthreads();

    float acc[8][4] = {};
    #pragma unroll
    for (int ks = 0; ks < 8; ++ks) {
        int k0 = ks * 8;
        unsigned a0 = s_A[(mr+g)*PADK + k0 + tig];
        unsigned a1 = s_A[(mr+g+8)*PADK + k0 + tig];
        unsigned a2 = s_A[(mr+g)*PADK + k0 + tig + 4];
        unsigned a3 = s_A[(mr+g+8)*PADK + k0 + tig + 4];
        #pragma unroll
        for (int nt = 0; nt < 8; ++nt) {
            unsigned b0 = s_W[(k0+tig)*72 + nt*8 + g];
            unsigned b1 = s_W[(k0+tig+4)*72 + nt*8 + g];
            mma_tf32(acc[nt][0], acc[nt][1], acc[nt][2], acc[nt][3], a0, a1, a2, a3, b0, b1);
        }
    }
    #pragma unroll
    for (int nt = 0; nt < 8; ++nt) {
        int col = nt*8 + 2*tig;
        float b0 = in_b[col], b1 = in_b[col+1];
        int r0 = rows0 + mr + g, r1 = r0 + 8;
        if (r0 < Nq) { float2 o = {(acc[nt][0]+b0)*0.25f, (acc[nt][1]+b1)*0.25f};
                       *(float2*)(g_q + r0*64 + col) = o; }
        if (r1 < Nq) { float2 o = {(acc[nt][2]+b0)*0.25f, (acc[nt][3]+b1)*0.25f};
                       *(float2*)(g_q + r1*64 + col) = o; }
    }
}

// ============================================================================
// attention kernel: 4 queries/block, 384 threads (12 warps), N-split across
// warps (0-5 K half, 6-11 V half, M=32 rows each), 2 CTAs/SM, fused gather.
// ============================================================================
#define SMEM_ATTN ((13056 + 8960 + 256 + 768 + 192) * 4)
__global__ __launch_bounds__(384, 2) void attn_kernel(
    const float* __restrict__ vf,     const float* __restrict__ vc,
    const float* __restrict__ qc,     const int*   __restrict__ kidx,
    const float* __restrict__ kpos_w, const float* __restrict__ kpos_b,
    const float* __restrict__ in_b)
{
    extern __shared__ unsigned smu[];
    unsigned* s_kfu = smu;                         // [192][68] tf32 A (alias vp float)
    unsigned* s_B2  = smu + 192 * PADK;            // ull[32][140] = 8960 words
    float*    s_q   = (float*)(s_B2 + 8960);       // 256
    float*    s_sc  = s_q + 256;                   // 768
    int*      s_idx = (int*)(s_sc + 768);          // 192

    const int tid  = threadIdx.x;
    const int lane = tid & 31;
    const int w    = tid >> 5;            // 0..11
    const int n0   = blockIdx.x * 4;

    // ---- phase 1: B2 copy + idx + q stage + gather ----
    for (int i = tid; i < 2240; i += 384)
        ((uint4*)s_B2)[i] = ((const uint4*)g_B2d)[i];
    if (tid < 192) s_idx[tid] = kidx[n0 * KK + tid];
    if (tid < 256) s_q[tid] = g_q[(n0 + (tid >> 6)) * 64 + (tid & 63)];
    {
        const int c2 = (tid & 31) * 2;
        const float ka0 = kpos_w[c2*3],   ka1 = kpos_w[c2*3+1], ka2 = kpos_w[c2*3+2];
        const float kb0 = kpos_w[c2*3+3], kb1 = kpos_w[c2*3+4], kb2 = kpos_w[c2*3+5];
        const float kba = kpos_b[c2], kbb = kpos_b[c2+1];
        for (int e = tid; e < 192 * 32; e += 384) {
            int kg = e >> 5;
            int n  = n0 + kg / KK;
            int idx = kidx[n0 * KK + kg];
            int safe = idx < 0 ? 0 : idx;
            float r0 = vc[safe*3+0] - qc[n*3+0];
            float r1 = vc[safe*3+1] - qc[n*3+1];
            float r2 = vc[safe*3+2] - qc[n*3+2];
            float2 f = *(const float2*)(vf + safe * 64 + c2);
            float p0 = kba + ka0*r0 + ka1*r1 + ka2*r2;
            float p1 = kbb + kb0*r0 + kb1*r1 + kb2*r2;
            uint2 o = { f2tf32(f.x + fmaxf(p0, 0.f)), f2tf32(f.y + fmaxf(p1, 0.f)) };
            *(uint2*)(s_kfu + kg * PADK + c2) = o;
        }
    }
    __syncthreads();

    const int g    = lane >> 2;
    const int tig  = lane & 3;
    const int half = (w >= 6);
    const int mw   = w - half * 6;
    const int mr   = mw * 32;
    const int cb   = half * 64;
    const unsigned long long* B2u = (const unsigned long long*)s_B2;

    float acc0[8][4], acc1[8][4];
    #pragma unroll
    for (int nt = 0; nt < 8; ++nt) {
        int cc = 8*nt + 2*tig;
        float b0 = in_b[64 + cb + cc], b1 = in_b[64 + cb + cc + 1];
        acc0[nt][0] = b0; acc0[nt][1] = b1; acc0[nt][2] = b0; acc0[nt][3] = b1;
        acc1[nt][0] = b0; acc1[nt][1] = b1; acc1[nt][2] = b0; acc1[nt][3] = b1;
    }
    #pragma unroll
    for (int ks = 0; ks < 8; ++ks) {
        const int k0 = ks * 8;
        unsigned a00 = s_kfu[(mr+g)*PADK + k0 + tig];
        unsigned a01 = s_kfu[(mr+g+8)*PADK + k0 + tig];
        unsigned a02 = s_kfu[(mr+g)*PADK + k0 + tig + 4];
        unsigned a03 = s_kfu[(mr+g+8)*PADK + k0 + tig + 4];
        unsigned a10 = s_kfu[(mr+g+16)*PADK + k0 + tig];
        unsigned a11 = s_kfu[(mr+g+24)*PADK + k0 + tig];
        unsigned a12 = s_kfu[(mr+g+16)*PADK + k0 + tig + 4];
        unsigned a13 = s_kfu[(mr+g+24)*PADK + k0 + tig + 4];
        const unsigned long long* bp = B2u + (ks*4 + tig) * BST + g + cb;
        #pragma unroll
        for (int nt = 0; nt < 8; ++nt) {
            unsigned long long pv = bp[nt * 8];
            unsigned b0 = (unsigned)pv, b1 = (unsigned)(pv >> 32);
            mma_tf32(acc0[nt][0], acc0[nt][1], acc0[nt][2], acc0[nt][3],
                     a00, a01, a02, a03, b0, b1);
            mma_tf32(acc1[nt][0], acc1[nt][1], acc1[nt][2], acc1[nt][3],
                     a10, a11, a12, a13, b0, b1);
        }
    }
    __syncthreads();   // all A reads complete before vp aliases kf

    if (half == 0) {
        #pragma unroll
        for (int t = 0; t < 2; ++t) {
            int r1 = mr + 16*t + g, r2 = r1 + 8;
            int q1 = r1 / KK, kk1 = r1 - q1 * KK;
            int q2 = r2 / KK, kk2 = r2 - q2 * KK;
            #pragma unroll
            for (int h = 0; h < 4; ++h) {
                int nA = 2*h, nB = 2*h + 1;
                int cA = 8*nA + 2*tig, cB = 8*nB + 2*tig;
                float qA0 = s_q[q1*64+cA], qA1 = s_q[q1*64+cA+1];
                float qB0 = s_q[q1*64+cB], qB1 = s_q[q1*64+cB+1];
                float qC0 = s_q[q2*64+cA], qC1 = s_q[q2*64+cA+1];
                float qD0 = s_q[q2*64+cB], qD1 = s_q[q2*64+cB+1];
                float s0, s1;
                if (t == 0) {
                    s0 = acc0[nA][0]*qA0 + acc0[nA][1]*qA1 + acc0[nB][0]*qB0 + acc0[nB][1]*qB1;
                    s1 = acc0[nA][2]*qC0 + acc0[nA][3]*qC1 + acc0[nB][2]*qD0 + acc0[nB][3]*qD1;
                } else {
                    s0 = acc1[nA][0]*qA0 + acc1[nA][1]*qA1 + acc1[nB][0]*qB0 + acc1[nB][1]*qB1;
                    s1 = acc1[nA][2]*qC0 + acc1[nA][3]*qC1 + acc1[nB][2]*qD0 + acc1[nB][3]*qD1;
                }
                s0 += __shfl_xor_sync(0xffffffffu, s0, 1);
                s0 += __shfl_xor_sync(0xffffffffu, s0, 2);
                s1 += __shfl_xor_sync(0xffffffffu, s1, 1);
                s1 += __shfl_xor_sync(0xffffffffu, s1, 2);
                if (tig == 0) {
                    s_sc[(q1*4+h)*48 + kk1] = (s_idx[r1] < 0) ? -1e30f : s0;
                    s_sc[(q2*4+h)*48 + kk2] = (s_idx[r2] < 0) ? -1e30f : s1;
                }
            }
        }
    } else {
        float* s_vp = (float*)s_kfu;
        #pragma unroll
        for (int t = 0; t < 2; ++t) {
            int r1 = mr + 16*t + g, r2 = r1 + 8;
            #pragma unroll
            for (int nt = 0; nt < 8; ++nt) {
                int cc = 8*nt + 2*tig;
                float2 o1, o2;
                if (t == 0) { o1 = make_float2(acc0[nt][0], acc0[nt][1]);
                              o2 = make_float2(acc0[nt][2], acc0[nt][3]); }
                else        { o1 = make_float2(acc1[nt][0], acc1[nt][1]);
                              o2 = make_float2(acc1[nt][2], acc1[nt][3]); }
                *(float2*)(s_vp + r1*PADK + cc) = o1;
                *(float2*)(s_vp + r2*PADK + cc) = o2;
            }
        }
    }
    __syncthreads();

    // ---- softmax (16 (q,h) rows over 12 warps) ----
    for (int r = w; r < 16; r += 12) {
        float* sc = s_sc + r * 48;
        float v0 = sc[lane];
        float v1 = (lane < 16) ? sc[32 + lane] : -1e30f;
        float m = fmaxf(v0, v1);
        #pragma unroll
        for (int o = 16; o > 0; o >>= 1) m = fmaxf(m, __shfl_xor_sync(0xffffffffu, m, o));
        float e0 = __expf(v0 - m);
        float e1 = (lane < 16) ? __expf(v1 - m) : 0.f;
        float s = e0 + e1;
        #pragma unroll
        for (int o = 16; o > 0; o >>= 1) s += __shfl_xor_sync(0xffffffffu, s, o);
        float inv = 1.f / s;
        sc[lane] = e0 * inv;
        if (lane < 16) sc[32 + lane] = e1 * inv;
    }
    __syncthreads();

    // ---- ctx = attn @ V -> g_ctx ----
    {
        const float* s_vp = (const float*)s_kfu;
        if (tid < 256) {
            int q = tid >> 6, c = tid & 63, h = c >> 4;
            const float* a  = s_sc + (q * 4 + h) * 48;
            const float* vp = s_vp + (q * 48) * PADK + c;
            float acc2 = 0.f;
            #pragma unroll 8
            for (int kk = 0; kk < KK; ++kk) acc2 = fmaf(a[kk], vp[kk * PADK], acc2);
            g_ctx[(n0 + q) * 64 + c] = acc2;
        }
    }
}

// ============================================================================
// ffn12 (fused ffn1+ffn2): att = ctx@Wo^T + out_b -> g_att (float) + smem tf32;
//                          hid = relu(att@W1^T + lin1_b) -> g_hid
// 64 rows/block, 256 threads.
// ============================================================================
#define SM_F12 ((4608 + 16896 + 64 * PADK) * 4)
__global__ __launch_bounds__(256) void ffn12_mma(
    const float* __restrict__ out_b, const float* __restrict__ lin1_b)
{
    extern __shared__ unsigned sm[];
    unsigned* s_Wo = sm;                   // [64][72]
    unsigned* s_W1 = sm + 4608;            // [64][264]
    unsigned* s_A  = sm + 4608 + 16896;    // [64][68]  ctx tf32, then att tf32
    const int tid = threadIdx.x, lane = tid & 31, w = tid >> 5;
    const int g = lane >> 2, tig = lane & 3;
    const int rows0 = blockIdx.x * 64;

    for (int i = tid; i < 1152; i += 256)
        ((uint4*)s_Wo)[i] = ((const uint4*)g_Wo)[i];
    for (int i = tid; i < 4224; i += 256)
        ((uint4*)s_W1)[i] = ((const uint4*)g_W1)[i];
    for (int i = tid; i < 64 * 64; i += 256) {
        int r = i >> 6, c = i & 63, row = rows0 + r;
        s_A[r * PADK + c] = f2tf32(row < Nq ? g_ctx[row * 64 + c] : 0.f);
    }
    __syncthreads();

    // ---- att phase: warp (w&3) -> rows, (w>>2) -> 32-col half ----
    {
        const int mr = (w & 3) * 16, nb = (w >> 2) * 32;
        float acc[4][4] = {};
        #pragma unroll
        for (int ks = 0; ks < 8; ++ks) {
            int k0 = ks * 8;
            unsigned a0 = s_A[(mr+g)*PADK + k0 + tig];
            unsigned a1 = s_A[(mr+g+8)*PADK + k0 + tig];
            unsigned a2 = s_A[(mr+g)*PADK + k0 + tig + 4];
            unsigned a3 = s_A[(mr+g+8)*PADK + k0 + tig + 4];
            #pragma unroll
            for (int nt = 0; nt < 4; ++nt) {
                unsigned b0 = s_Wo[(k0+tig)*72 + nb + nt*8 + g];
                unsigned b1 = s_Wo[(k0+tig+4)*72 + nb + nt*8 + g];
                mma_tf32(acc[nt][0], acc[nt][1], acc[nt][2], acc[nt][3], a0, a1, a2, a3, b0, b1);
            }
        }
        __syncthreads();   // all ctx reads done before att overwrites s_A
        #pragma unroll
        for (int nt = 0; nt < 4; ++nt) {
            int col = nb + nt*8 + 2*tig;
            float b0 = out_b[col], b1 = out_b[col+1];
            int lr0 = mr + g, lr1 = lr0 + 8;
            int r0 = rows0 + lr0, r1 = rows0 + lr1;
            float x00 = acc[nt][0] + b0, x01 = acc[nt][1] + b1;
            float x10 = acc[nt][2] + b0, x11 = acc[nt][3] + b1;
            if (r0 < Nq) { float2 o = {x00, x01}; *(float2*)(g_att + r0*64 + col) = o; }
            if (r1 < Nq) { float2 o = {x10, x11}; *(float2*)(g_att + r1*64 + col) = o; }
            s_A[lr0 * PADK + col]     = f2tf32(x00);
            s_A[lr0 * PADK + col + 1] = f2tf32(x01);
            s_A[lr1 * PADK + col]     = f2tf32(x10);
            s_A[lr1 * PADK + col + 1] = f2tf32(x11);
        }
    }
    __syncthreads();

    // ---- hid phase: warp (w&3) -> rows, (w>>2) -> 128-col half ----
    {
        const int mr = (w & 3) * 16, nbase = (w >> 2) * 128;
        float acc[16][4];
        #pragma unroll
        for (int nt = 0; nt < 16; ++nt)
            #pragma unroll
            for (int j = 0; j < 4; ++j) acc[nt][j] = 0.f;

        #pragma unroll
        for (int ks = 0; ks < 8; ++ks) {
            int k0 = ks * 8;
            unsigned a0 = s_A[(mr+g)*PADK + k0 + tig];
            unsigned a1 = s_A[(mr+g+8)*PADK + k0 + tig];
            unsigned a2 = s_A[(mr+g)*PADK + k0 + tig + 4];
            unsigned a3 = s_A[(mr+g+8)*PADK + k0 + tig + 4];
            #pragma unroll
            for (int nt = 0; nt < 16; ++nt) {
                unsigned b0 = s_W1[(k0+tig)*264 + nbase + nt*8 + g];
                unsigned b1 = s_W1[(k0+tig+4)*264 + nbase + nt*8 + g];
                mma_tf32(acc[nt][0], acc[nt][1], acc[nt][2], acc[nt][3], a0, a1, a2, a3, b0, b1);
            }
        }
        #pragma unroll
        for (int nt = 0; nt < 16; ++nt) {
            int col = nbase + nt*8 + 2*tig;
            float b0 = lin1_b[col], b1 = lin1_b[col+1];
            int r0 = rows0 + mr + g, r1 = r0 + 8;
            if (r0 < Nq) { float2 o = {fmaxf(acc[nt][0]+b0, 0.f), fmaxf(acc[nt][1]+b1, 0.f)};
                           *(float2*)(g_hid + r0*256 + col) = o; }
            if (r1 < Nq) { float2 o = {fmaxf(acc[nt][2]+b0, 0.f), fmaxf(acc[nt][3]+b1, 0.f)};
                           *(float2*)(g_hid + r1*256 + col) = o; }
        }
    }
}

// ============================================================================
// ffn3: g_x = g_att + g_hid @ lin2_w^T + lin2_b, BN1 stats
// ============================================================================
#define SM_F3 ((256 * 72 + 128 * PADK + 128) * 4)
__global__ __launch_bounds__(256) void ffn3_mma(const float* __restrict__ lin2_b)
{
    extern __shared__ unsigned sm[];
    unsigned* s_W = sm;               // [256][72]
    unsigned* s_A = sm + 256 * 72;    // [128][68]
    float* s_ps = (float*)(s_A + 128 * PADK);
    float* s_pq = s_ps + 64;
    const int tid = threadIdx.x, lane = tid & 31, w = tid >> 5;
    const int g = lane >> 2, tig = lane & 3, mr = w * 16;
    const int rows0 = blockIdx.x * 128;

    if (tid < 64) { s_ps[tid] = 0.f; s_pq[tid] = 0.f; }
    for (int i = tid; i < 4608; i += 256)
        ((uint4*)s_W)[i] = ((const uint4*)g_W2)[i];

    float acc[8][4] = {};
    for (int kc = 0; kc < 4; ++kc) {
        __syncthreads();
        for (int i = tid; i < 128 * 64; i += 256) {
            int r = i >> 6, c = i & 63, row = rows0 + r;
            s_A[r * PADK + c] = f2tf32(row < Nq ? g_hid[row * 256 + kc * 64 + c] : 0.f);
        }
        __syncthreads();
        #pragma unroll
        for (int ks = 0; ks < 8; ++ks) {
            int k0 = ks * 8;
            unsigned a0 = s_A[(mr+g)*PADK + k0 + tig];
            unsigned a1 = s_A[(mr+g+8)*PADK + k0 + tig];
            unsigned a2 = s_A[(mr+g)*PADK + k0 + tig + 4];
            unsigned a3 = s_A[(mr+g+8)*PADK + k0 + tig + 4];
            int kw = kc * 64 + k0;
            #pragma unroll
            for (int nt = 0; nt < 8; ++nt) {
                unsigned b0 = s_W[(kw+tig)*72 + nt*8 + g];
                unsigned b1 = s_W[(kw+tig+4)*72 + nt*8 + g];
                mma_tf32(acc[nt][0], acc[nt][1], acc[nt][2], acc[nt][3], a0, a1, a2, a3, b0, b1);
            }
        }
    }

    #pragma unroll
    for (int nt = 0; nt < 8; ++nt) {
        int col = nt*8 + 2*tig;
        float b0 = lin2_b[col], b1 = lin2_b[col+1];
        int r0 = rows0 + mr + g, r1 = r0 + 8;
        bool v0 = r0 < Nq, v1 = r1 < Nq;
        float2 a0r = v0 ? *(const float2*)(g_att + r0*64 + col) : make_float2(0.f, 0.f);
        float2 a1r = v1 ? *(const float2*)(g_att + r1*64 + col) : make_float2(0.f, 0.f);
        float x00 = acc[nt][0] + b0 + a0r.x, x01 = acc[nt][1] + b1 + a0r.y;
        float x10 = acc[nt][2] + b0 + a1r.x, x11 = acc[nt][3] + b1 + a1r.y;
        if (v0) { float2 o = {x00, x01}; *(float2*)(g_x + r0*64 + col) = o; }
        if (v1) { float2 o = {x10, x11}; *(float2*)(g_x + r1*64 + col) = o; }
        float m00 = v0 ? x00 : 0.f, m01 = v0 ? x01 : 0.f;
        float m10 = v1 ? x10 : 0.f, m11 = v1 ? x11 : 0.f;
        float se = m00 + m10,                 so = m01 + m11;
        float sq = m00*m00 + m10*m10,         qo = m01*m01 + m11*m11;
        #pragma unroll
        for (int o = 16; o >= 4; o >>= 1) {
            se += __shfl_down_sync(0xffffffffu, se, o);
            so += __shfl_down_sync(0xffffffffu, so, o);
            sq += __shfl_down_sync(0xffffffffu, sq, o);
            qo += __shfl_down_sync(0xffffffffu, qo, o);
        }
        if (lane < 4) {
            atomicAdd(&s_ps[col], se);  atomicAdd(&s_pq[col], sq);
            atomicAdd(&s_ps[col+1], so); atomicAdd(&s_pq[col+1], qo);
        }
    }
    __syncthreads();
    if (tid < 64) {
        atomicAdd(&g_sum1[tid], (double)s_ps[tid]);
        atomicAdd(&g_sq1[tid],  (double)s_pq[tid]);
    }
}

// ============================================================================
// proj: g_z = BN1(g_x) @ outl_w^T + outl_b, BN2 stats. Inlines BN1 finalize
// (157 blocks — cheap).
// ============================================================================
#define SM_P ((64 * 72 + 128 * PADK + 256) * 4)
__global__ __launch_bounds__(256) void proj_mma(
    const float* __restrict__ outl_b,
    const float* __restrict__ norm_g, const float* __restrict__ norm_b)
{
    extern __shared__ unsigned sm[];
    unsigned* s_W = sm;
    unsigned* s_A = sm + 64 * 72;
    float* s_ps = (float*)(s_A + 128 * PADK);
    float* s_pq = s_ps + 64;
    float* s_mu = s_pq + 64;
    float* s_rs = s_mu + 64;
    const int tid = threadIdx.x, lane = tid & 31, w = tid >> 5;
    const int g = lane >> 2, tig = lane & 3, mr = w * 16;
    const int rows0 = blockIdx.x * 128;

    if (tid < 64) {
        s_ps[tid] = 0.f; s_pq[tid] = 0.f;
        double m = g_sum1[tid] / (double)Nq;
        double v = g_sq1[tid] / (double)Nq - m * m;
        if (v < 0) v = 0;
        s_mu[tid] = (float)m;
        s_rs[tid] = (float)(1.0 / sqrt(v + 1e-5));
    }
    for (int i = tid; i < 1152; i += 256)
        ((uint4*)s_W)[i] = ((const uint4*)g_Wl)[i];
    __syncthreads();
    {
        const int c = tid & 63;
        const float mu = s_mu[c], rs = s_rs[c], ga = norm_g[c], be = norm_b[c];
        for (int i = tid; i < 128 * 64; i += 256) {
            int r = i >> 6, row = rows0 + r;
            float v = 0.f;
            if (row < Nq) v = (g_x[row * 64 + c] - mu) * rs * ga + be;
            s_A[r * PADK + c] = f2tf32(v);
        }
    }
    __syncthreads();

    float acc[8][4] = {};
    #pragma unroll
    for (int ks = 0; ks < 8; ++ks) {
        int k0 = ks * 8;
        unsigned a0 = s_A[(mr+g)*PADK + k0 + tig];
        unsigned a1 = s_A[(mr+g+8)*PADK + k0 + tig];
        unsigned a2 = s_A[(mr+g)*PADK + k0 + tig + 4];
        unsigned a3 = s_A[(mr+g+8)*PADK + k0 + tig + 4];
        #pragma unroll
        for (int nt = 0; nt < 8; ++nt) {
            unsigned b0 = s_W[(k0+tig)*72 + nt*8 + g];
            unsigned b1 = s_W[(k0+tig+4)*72 + nt*8 + g];
            mma_tf32(acc[nt][0], acc[nt][1], acc[nt][2], acc[nt][3], a0, a1, a2, a3, b0, b1);
        }
    }
    #pragma unroll
    for (int nt = 0; nt < 8; ++nt) {
        int col = nt*8 + 2*tig;
        float b0 = outl_b[col], b1 = outl_b[col+1];
        int r0 = rows0 + mr + g, r1 = r0 + 8;
        bool v0 = r0 < Nq, v1 = r1 < Nq;
        float x00 = acc[nt][0] + b0, x01 = acc[nt][1] + b1;
        float x10 = acc[nt][2] + b0, x11 = acc[nt][3] + b1;
        if (v0) { float2 o = {x00, x01}; *(float2*)(g_z + r0*64 + col) = o; }
        if (v1) { float2 o = {x10, x11}; *(float2*)(g_z + r1*64 + col) = o; }
        float m00 = v0 ? x00 : 0.f, m01 = v0 ? x01 : 0.f;
        float m10 = v1 ? x10 : 0.f, m11 = v1 ? x11 : 0.f;
        float se = m00 + m10,                 so = m01 + m11;
        float sq = m00*m00 + m10*m10,         qo = m01*m01 + m11*m11;
        #pragma unroll
        for (int o = 16; o >= 4; o >>= 1) {
            se += __shfl_down_sync(0xffffffffu, se, o);
            so += __shfl_down_sync(0xffffffffu, so, o);
            sq += __shfl_down_sync(0xffffffffu, sq, o);
            qo += __shfl_down_sync(0xffffffffu, qo, o);
        }
        if (lane < 4) {
            atomicAdd(&s_ps[col], se);  atomicAdd(&s_pq[col], sq);
            atomicAdd(&s_ps[col+1], so); atomicAdd(&s_pq[col+1], qo);
        }
    }
    __syncthreads();
    if (tid < 64) {
        atomicAdd(&g_sum2[tid], (double)s_ps[tid]);
        atomicAdd(&g_sq2[tid],  (double)s_pq[tid]);
    }
}

__global__ void finalize2_kernel() {
    int t = threadIdx.x;
    if (t < 64) {
        double m = g_sum2[t] / (double)Nq;
        double v = g_sq2[t] / (double)Nq - m * m;
        if (v < 0) v = 0;
        g_mu2[t] = (float)m;
        g_rs2[t] = (float)(1.0 / sqrt(v + 1e-5));
    }
}

// ============================================================================
// final: BN2 + relu -> out (reads precomputed float stats)
// ============================================================================
__global__ void final_kernel(float* __restrict__ out,
                             const float* __restrict__ obn_g,
                             const float* __restrict__ obn_b)
{
    int i = blockIdx.x * 256 + threadIdx.x;
    if (i < Nq * 64) {
        int o = i & 63;
        float v = (g_z[i] - g_mu2[o]) * g_rs2[o] * obn_g[o] + obn_b[o];
        out[i] = fmaxf(v, 0.f);
    }
}

extern "C" void kernel_launch(void* const* d_in, const int* in_sizes, int n_in,
                              void* d_out, int out_size) {
    const float* vf     = (const float*)d_in[0];
    const float* vc     = (const float*)d_in[1];
    const float* qcoord = (const float*)d_in[2];
    const int*   kidx   = (const int*)  d_in[3];
    const float* q_w    = (const float*)d_in[4];
    const float* q_b    = (const float*)d_in[5];
    const float* kpos_w = (const float*)d_in[6];
    const float* kpos_b = (const float*)d_in[7];
    const float* in_w   = (const float*)d_in[8];
    const float* in_b   = (const float*)d_in[9];
    const float* out_w  = (const float*)d_in[10];
    const float* out_b  = (const float*)d_in[11];
    const float* lin1_w = (const float*)d_in[12];
    const float* lin1_b = (const float*)d_in[13];
    const float* lin2_w = (const float*)d_in[14];
    const float* lin2_b = (const float*)d_in[15];
    const float* norm_g = (const float*)d_in[16];
    const float* norm_b = (const float*)d_in[17];
    const float* outl_w = (const float*)d_in[18];
    const float* outl_b = (const float*)d_in[19];
    const float* obn_g  = (const float*)d_in[20];
    const float* obn_b  = (const float*)d_in[21];
    float* out = (float*)d_out;

    cudaFuncSetAttribute(attn_kernel, cudaFuncAttributeMaxDynamicSharedMemorySize, SMEM_ATTN);
    cudaFuncSetAttribute(qproj_mma,   cudaFuncAttributeMaxDynamicSharedMemorySize, SM_Q);
    cudaFuncSetAttribute(ffn12_mma,   cudaFuncAttributeMaxDynamicSharedMemorySize, SM_F12);
    cudaFuncSetAttribute(ffn3_mma,    cudaFuncAttributeMaxDynamicSharedMemorySize, SM_F3);
    cudaFuncSetAttribute(proj_mma,    cudaFuncAttributeMaxDynamicSharedMemorySize, SM_P);

    const int RB = (Nq + 127) / 128;    // 157

    prep_kernel<<<13, 256>>>(in_w, out_w, lin1_w, lin2_w, outl_w);   // launch 1
    zero_stats<<<1, 64>>>();                                         // launch 2
    qproj_mma<<<RB, 256, SM_Q>>>(qcoord, q_w, q_b, in_b);            // launch 3
    attn_kernel<<<Nq / 4, 384, SMEM_ATTN>>>(vf, vc, qcoord, kidx,
                                            kpos_w, kpos_b, in_b);   // launch 4 (ncu)
    ffn12_mma<<<(Nq + 63) / 64, 256, SM_F12>>>(out_b, lin1_b);
    ffn3_mma<<<RB, 256, SM_F3>>>(lin2_b);
    proj_mma<<<RB, 256, SM_P>>>(outl_b, norm_g, norm_b);
    finalize2_kernel<<<1, 64>>>();
    final_kernel<<<(Nq * 64 + 255) / 256, 256>>>(out, obn_g, obn_b);
}

// round 16
// speedup vs baseline: 1.3591x; 1.0131x over previous
#include <cuda_runtime.h>
#include <math.h>

#define Nq   20000
#define KK   48
#define PADK 68
#define BST  132   // B2 ull row stride (conflict-free: 2*132*tig mod 32 = {0,8,16,24})

// ---- scratch ----
__device__ float  g_q[Nq * 64];
__device__ float  g_ctx[Nq * 64];
__device__ float  g_att[Nq * 64];
__device__ float  g_hid[Nq * 256];
__device__ float  g_x[Nq * 64];
__device__ float  g_z[Nq * 64];
__device__ double g_sum1[64], g_sq1[64];
__device__ double g_sum2[64], g_sq2[64];
__device__ float  g_mu2[64], g_rs2[64];
// pre-converted tf32 weights (padded layouts)
__device__ unsigned long long g_B2d[32 * BST];
__device__ unsigned g_Wq[64 * 72];
__device__ unsigned g_Wo[64 * 72];
__device__ unsigned g_W1[64 * 264];
__device__ unsigned g_W2[256 * 72];
__device__ unsigned g_Wl[64 * 72];

__device__ __forceinline__ unsigned f2tf32(float x) {
    unsigned r; asm("cvt.rna.tf32.f32 %0, %1;" : "=r"(r) : "f"(x)); return r;
}
__device__ __forceinline__ void mma_tf32(float& d0, float& d1, float& d2, float& d3,
                                         unsigned a0, unsigned a1, unsigned a2, unsigned a3,
                                         unsigned b0, unsigned b1) {
    asm volatile("mma.sync.aligned.m16n8k8.row.col.f32.tf32.tf32.f32 "
                 "{%0,%1,%2,%3}, {%4,%5,%6,%7}, {%8,%9}, {%0,%1,%2,%3};"
                 : "+f"(d0), "+f"(d1), "+f"(d2), "+f"(d3)
                 : "r"(a0), "r"(a1), "r"(a2), "r"(a3), "r"(b0), "r"(b1));
}

// ============================================================================
// prep: convert weights to tf32 padded layouts (once per launch)
// ============================================================================
__global__ __launch_bounds__(256) void prep_kernel(
    const float* __restrict__ in_w,  const float* __restrict__ out_w,
    const float* __restrict__ lin1_w, const float* __restrict__ lin2_w,
    const float* __restrict__ outl_w)
{
    const int tid = threadIdx.x, b = blockIdx.x;
    if (b == 0) {
        for (int i = tid; i < 4096; i += 256) {
            int n = i >> 6, k = i & 63;
            g_Wq[k * 72 + n] = f2tf32(in_w[n * 64 + k]);
        }
    } else if (b <= 2) {             // B2: in_w rows 64..191 (K|V), packed pairs
        for (int i = (b - 1) * 4096 + tid; i < b * 4096; i += 256) {
            int n = i >> 6, k = i & 63;
            int ks = k >> 3, rem = k & 7, tg = rem & 3, slot = rem >> 2;
            ((unsigned*)g_B2d)[(((ks*4+tg)*BST) + n) * 2 + slot] = f2tf32(in_w[4096 + i]);
        }
    } else if (b == 3) {
        for (int i = tid; i < 4096; i += 256) {
            int n = i >> 6, k = i & 63;
            g_Wo[k * 72 + n] = f2tf32(out_w[n * 64 + k]);
        }
    } else if (b <= 7) {
        for (int i = (b - 4) * 4096 + tid; i < (b - 3) * 4096; i += 256) {
            int n = i >> 6, k = i & 63;
            g_W1[k * 264 + n] = f2tf32(lin1_w[n * 64 + k]);
        }
    } else if (b <= 11) {
        for (int i = (b - 8) * 4096 + tid; i < (b - 7) * 4096; i += 256) {
            int k = i >> 6, n = i & 63;
            g_W2[k * 72 + n] = f2tf32(lin2_w[n * 256 + k]);
        }
    } else {
        for (int i = tid; i < 4096; i += 256) {
            int n = i >> 6, k = i & 63;
            g_Wl[k * 72 + n] = f2tf32(outl_w[n * 64 + k]);
        }
    }
}

__global__ void zero_stats() {
    int t = threadIdx.x;
    if (t < 64) { g_sum1[t] = 0.0; g_sq1[t] = 0.0; g_sum2[t] = 0.0; g_sq2[t] = 0.0; }
}

// ============================================================================
// qproj
// ============================================================================
#define SM_Q ((64 * 72 + 128 * PADK) * 4)
__global__ __launch_bounds__(256) void qproj_mma(
    const float* __restrict__ qc, const float* __restrict__ q_w, const float* __restrict__ q_b,
    const float* __restrict__ in_b)
{
    extern __shared__ unsigned sm[];
    unsigned* s_W = sm;
    unsigned* s_A = sm + 64 * 72;
    const int tid = threadIdx.x, lane = tid & 31, w = tid >> 5;
    const int g = lane >> 2, tig = lane & 3, mr = w * 16;
    const int rows0 = blockIdx.x * 128;

    for (int i = tid; i < 1152; i += 256)
        ((uint4*)s_W)[i] = ((const uint4*)g_Wq)[i];
    {
        const int c = tid & 63;
        const float w0 = q_w[c*3], w1 = q_w[c*3+1], w2 = q_w[c*3+2], b = q_b[c];
        for (int i = tid; i < 128 * 64; i += 256) {
            int r = i >> 6, row = rows0 + r;
            float v = 0.f;
            if (row < Nq)
                v = fmaxf(b + w0*qc[row*3] + w1*qc[row*3+1] + w2*qc[row*3+2], 0.f);
            s_A[r * PADK + c] = f2tf32(v);
        }
    }
    __syncthreads();

    float acc[8][4] = {};
    #pragma unroll
    for (int ks = 0; ks < 8; ++ks) {
        int k0 = ks * 8;
        unsigned a0 = s_A[(mr+g)*PADK + k0 + tig];
        unsigned a1 = s_A[(mr+g+8)*PADK + k0 + tig];
        unsigned a2 = s_A[(mr+g)*PADK + k0 + tig + 4];
        unsigned a3 = s_A[(mr+g+8)*PADK + k0 + tig + 4];
        #pragma unroll
        for (int nt = 0; nt < 8; ++nt) {
            unsigned b0 = s_W[(k0+tig)*72 + nt*8 + g];
            unsigned b1 = s_W[(k0+tig+4)*72 + nt*8 + g];
            mma_tf32(acc[nt][0], acc[nt][1], acc[nt][2], acc[nt][3], a0, a1, a2, a3, b0, b1);
        }
    }
    #pragma unroll
    for (int nt = 0; nt < 8; ++nt) {
        int col = nt*8 + 2*tig;
        float b0 = in_b[col], b1 = in_b[col+1];
        int r0 = rows0 + mr + g, r1 = r0 + 8;
        if (r0 < Nq) { float2 o = {(acc[nt][0]+b0)*0.25f, (acc[nt][1]+b1)*0.25f};
                       *(float2*)(g_q + r0*64 + col) = o; }
        if (r1 < Nq) { float2 o = {(acc[nt][2]+b0)*0.25f, (acc[nt][3]+b1)*0.25f};
                       *(float2*)(g_q + r1*64 + col) = o; }
    }
}

// ============================================================================
// attention kernel: 4 queries/block, 384 threads (12 warps), N-split across
// warps (0-5 K half, 6-11 V half, M=32 rows each), 2 CTAs/SM.
// Softmax fused into ctx (warp-local, one fewer block barrier).
// ============================================================================
// smem words: kf 13056 | B2 8448 | q 256 | sc 768 | rel 576 | idx 192
#define SMEM_ATTN ((13056 + 2*BST*32 + 256 + 768 + 576 + 192) * 4)
__global__ __launch_bounds__(384, 2) void attn_kernel(
    const float* __restrict__ vf,     const float* __restrict__ vc,
    const float* __restrict__ qc,     const int*   __restrict__ kidx,
    const float* __restrict__ kpos_w, const float* __restrict__ kpos_b,
    const float* __restrict__ in_b)
{
    extern __shared__ unsigned smu[];
    unsigned* s_kfu = smu;                         // [192][68] tf32 A (alias vp float)
    unsigned* s_B2  = smu + 192 * PADK;            // ull[32][132] = 8448 words
    float*    s_q   = (float*)(s_B2 + 2*BST*32);   // 256
    float*    s_sc  = s_q + 256;                   // 768
    float*    s_rel = s_sc + 768;                  // 576
    int*      s_idx = (int*)(s_rel + 576);         // 192

    const int tid  = threadIdx.x;
    const int lane = tid & 31;
    const int w    = tid >> 5;            // 0..11
    const int n0   = blockIdx.x * 4;

    // ---- staging ----
    for (int i = tid; i < 2112; i += 384)
        ((uint4*)s_B2)[i] = ((const uint4*)g_B2d)[i];
    if (tid < 192) {
        int q = tid / KK, kk = tid - q * KK;
        int n = n0 + q;
        int idx = kidx[n * KK + kk];
        s_idx[tid] = idx;
        int safe = idx < 0 ? 0 : idx;
        s_rel[tid*3+0] = vc[safe*3+0] - qc[n*3+0];
        s_rel[tid*3+1] = vc[safe*3+1] - qc[n*3+1];
        s_rel[tid*3+2] = vc[safe*3+2] - qc[n*3+2];
    }
    if (tid < 256) s_q[tid] = g_q[(n0 + (tid >> 6)) * 64 + (tid & 63)];
    __syncthreads();

    // ---- gather key features (tf32, float2-vectorized) ----
    {
        const int c2 = (tid & 31) * 2;
        const float ka0 = kpos_w[c2*3],   ka1 = kpos_w[c2*3+1], ka2 = kpos_w[c2*3+2];
        const float kb0 = kpos_w[c2*3+3], kb1 = kpos_w[c2*3+4], kb2 = kpos_w[c2*3+5];
        const float kba = kpos_b[c2], kbb = kpos_b[c2+1];
        for (int e = tid; e < 192 * 32; e += 384) {
            int kg = e >> 5;
            int idx = s_idx[kg]; if (idx < 0) idx = 0;
            float2 f = *(const float2*)(vf + idx * 64 + c2);
            float r0 = s_rel[kg*3], r1 = s_rel[kg*3+1], r2 = s_rel[kg*3+2];
            float p0 = kba + ka0*r0 + ka1*r1 + ka2*r2;
            float p1 = kbb + kb0*r0 + kb1*r1 + kb2*r2;
            uint2 o = { f2tf32(f.x + fmaxf(p0, 0.f)), f2tf32(f.y + fmaxf(p1, 0.f)) };
            *(uint2*)(s_kfu + kg * PADK + c2) = o;
        }
    }
    __syncthreads();

    const int g    = lane >> 2;
    const int tig  = lane & 3;
    const int half = (w >= 6);
    const int mw   = w - half * 6;
    const int mr   = mw * 32;
    const int cb   = half * 64;
    const unsigned long long* B2u = (const unsigned long long*)s_B2;

    float acc0[8][4], acc1[8][4];
    #pragma unroll
    for (int nt = 0; nt < 8; ++nt) {
        int cc = 8*nt + 2*tig;
        float b0 = in_b[64 + cb + cc], b1 = in_b[64 + cb + cc + 1];
        acc0[nt][0] = b0; acc0[nt][1] = b1; acc0[nt][2] = b0; acc0[nt][3] = b1;
        acc1[nt][0] = b0; acc1[nt][1] = b1; acc1[nt][2] = b0; acc1[nt][3] = b1;
    }
    #pragma unroll
    for (int ks = 0; ks < 8; ++ks) {
        const int k0 = ks * 8;
        unsigned a00 = s_kfu[(mr+g)*PADK + k0 + tig];
        unsigned a01 = s_kfu[(mr+g+8)*PADK + k0 + tig];
        unsigned a02 = s_kfu[(mr+g)*PADK + k0 + tig + 4];
        unsigned a03 = s_kfu[(mr+g+8)*PADK + k0 + tig + 4];
        unsigned a10 = s_kfu[(mr+g+16)*PADK + k0 + tig];
        unsigned a11 = s_kfu[(mr+g+24)*PADK + k0 + tig];
        unsigned a12 = s_kfu[(mr+g+16)*PADK + k0 + tig + 4];
        unsigned a13 = s_kfu[(mr+g+24)*PADK + k0 + tig + 4];
        const unsigned long long* bp = B2u + (ks*4 + tig) * BST + g + cb;
        #pragma unroll
        for (int nt = 0; nt < 8; ++nt) {
            unsigned long long pv = bp[nt * 8];
            unsigned b0 = (unsigned)pv, b1 = (unsigned)(pv >> 32);
            mma_tf32(acc0[nt][0], acc0[nt][1], acc0[nt][2], acc0[nt][3],
                     a00, a01, a02, a03, b0, b1);
            mma_tf32(acc1[nt][0], acc1[nt][1], acc1[nt][2], acc1[nt][3],
                     a10, a11, a12, a13, b0, b1);
        }
    }
    __syncthreads();   // all A reads complete before vp aliases kf

    if (half == 0) {
        #pragma unroll
        for (int t = 0; t < 2; ++t) {
            int r1 = mr + 16*t + g, r2 = r1 + 8;
            int q1 = r1 / KK, kk1 = r1 - q1 * KK;
            int q2 = r2 / KK, kk2 = r2 - q2 * KK;
            #pragma unroll
            for (int h = 0; h < 4; ++h) {
                int nA = 2*h, nB = 2*h + 1;
                int cA = 8*nA + 2*tig, cB = 8*nB + 2*tig;
                float qA0 = s_q[q1*64+cA], qA1 = s_q[q1*64+cA+1];
                float qB0 = s_q[q1*64+cB], qB1 = s_q[q1*64+cB+1];
                float qC0 = s_q[q2*64+cA], qC1 = s_q[q2*64+cA+1];
                float qD0 = s_q[q2*64+cB], qD1 = s_q[q2*64+cB+1];
                float s0, s1;
                if (t == 0) {
                    s0 = acc0[nA][0]*qA0 + acc0[nA][1]*qA1 + acc0[nB][0]*qB0 + acc0[nB][1]*qB1;
                    s1 = acc0[nA][2]*qC0 + acc0[nA][3]*qC1 + acc0[nB][2]*qD0 + acc0[nB][3]*qD1;
                } else {
                    s0 = acc1[nA][0]*qA0 + acc1[nA][1]*qA1 + acc1[nB][0]*qB0 + acc1[nB][1]*qB1;
                    s1 = acc1[nA][2]*qC0 + acc1[nA][3]*qC1 + acc1[nB][2]*qD0 + acc1[nB][3]*qD1;
                }
                s0 += __shfl_xor_sync(0xffffffffu, s0, 1);
                s0 += __shfl_xor_sync(0xffffffffu, s0, 2);
                s1 += __shfl_xor_sync(0xffffffffu, s1, 1);
                s1 += __shfl_xor_sync(0xffffffffu, s1, 2);
                if (tig == 0) {
                    s_sc[(q1*4+h)*48 + kk1] = (s_idx[r1] < 0) ? -1e30f : s0;
                    s_sc[(q2*4+h)*48 + kk2] = (s_idx[r2] < 0) ? -1e30f : s1;
                }
            }
        }
    } else {
        float* s_vp = (float*)s_kfu;
        #pragma unroll
        for (int t = 0; t < 2; ++t) {
            int r1 = mr + 16*t + g, r2 = r1 + 8;
            #pragma unroll
            for (int nt = 0; nt < 8; ++nt) {
                int cc = 8*nt + 2*tig;
                float2 o1, o2;
                if (t == 0) { o1 = make_float2(acc0[nt][0], acc0[nt][1]);
                              o2 = make_float2(acc0[nt][2], acc0[nt][3]); }
                else        { o1 = make_float2(acc1[nt][0], acc1[nt][1]);
                              o2 = make_float2(acc1[nt][2], acc1[nt][3]); }
                *(float2*)(s_vp + r1*PADK + cc) = o1;
                *(float2*)(s_vp + r2*PADK + cc) = o2;
            }
        }
    }
    __syncthreads();

    // ---- fused softmax + ctx: warp w<8 owns (q = w>>1, c-half = w&1),
    //      softmaxes exactly the two (q,h) rows its ctx slice consumes ----
    if (w < 8) {
        const int q  = w >> 1;
        const int ch = w & 1;
        #pragma unroll
        for (int hh = 0; hh < 2; ++hh) {
            int r = q * 4 + ch * 2 + hh;
            float* sc = s_sc + r * 48;
            float v0 = sc[lane];
            float v1 = (lane < 16) ? sc[32 + lane] : -1e30f;
            float m = fmaxf(v0, v1);
            #pragma unroll
            for (int o = 16; o > 0; o >>= 1) m = fmaxf(m, __shfl_xor_sync(0xffffffffu, m, o));
            float e0 = __expf(v0 - m);
            float e1 = (lane < 16) ? __expf(v1 - m) : 0.f;
            float s = e0 + e1;
            #pragma unroll
            for (int o = 16; o > 0; o >>= 1) s += __shfl_xor_sync(0xffffffffu, s, o);
            float inv = 1.f / s;
            sc[lane] = e0 * inv;
            if (lane < 16) sc[32 + lane] = e1 * inv;
        }
        __syncwarp();
        const float* s_vp = (const float*)s_kfu;
        int c = ch * 32 + lane, h = c >> 4;
        const float* a  = s_sc + (q * 4 + h) * 48;
        const float* vp = s_vp + (q * 48) * PADK + c;
        float acc2 = 0.f;
        #pragma unroll 8
        for (int kk = 0; kk < KK; ++kk) acc2 = fmaf(a[kk], vp[kk * PADK], acc2);
        g_ctx[(n0 + q) * 64 + c] = acc2;
    }
}

// ============================================================================
// ffn1: g_att = g_ctx @ out_w^T + out_b
// ============================================================================
#define SM_F1 ((64 * 72 + 128 * PADK) * 4)
__global__ __launch_bounds__(256) void ffn1_mma(const float* __restrict__ out_b)
{
    extern __shared__ unsigned sm[];
    unsigned* s_W = sm;
    unsigned* s_A = sm + 64 * 72;
    const int tid = threadIdx.x, lane = tid & 31, w = tid >> 5;
    const int g = lane >> 2, tig = lane & 3, mr = w * 16;
    const int rows0 = blockIdx.x * 128;

    for (int i = tid; i < 1152; i += 256)
        ((uint4*)s_W)[i] = ((const uint4*)g_Wo)[i];
    for (int i = tid; i < 128 * 64; i += 256) {
        int r = i >> 6, c = i & 63, row = rows0 + r;
        s_A[r * PADK + c] = f2tf32(row < Nq ? g_ctx[row * 64 + c] : 0.f);
    }
    __syncthreads();

    float acc[8][4] = {};
    #pragma unroll
    for (int ks = 0; ks < 8; ++ks) {
        int k0 = ks * 8;
        unsigned a0 = s_A[(mr+g)*PADK + k0 + tig];
        unsigned a1 = s_A[(mr+g+8)*PADK + k0 + tig];
        unsigned a2 = s_A[(mr+g)*PADK + k0 + tig + 4];
        unsigned a3 = s_A[(mr+g+8)*PADK + k0 + tig + 4];
        #pragma unroll
        for (int nt = 0; nt < 8; ++nt) {
            unsigned b0 = s_W[(k0+tig)*72 + nt*8 + g];
            unsigned b1 = s_W[(k0+tig+4)*72 + nt*8 + g];
            mma_tf32(acc[nt][0], acc[nt][1], acc[nt][2], acc[nt][3], a0, a1, a2, a3, b0, b1);
        }
    }
    #pragma unroll
    for (int nt = 0; nt < 8; ++nt) {
        int col = nt*8 + 2*tig;
        float b0 = out_b[col], b1 = out_b[col+1];
        int r0 = rows0 + mr + g, r1 = r0 + 8;
        if (r0 < Nq) { float2 o = {acc[nt][0]+b0, acc[nt][1]+b1};
                       *(float2*)(g_att + r0*64 + col) = o; }
        if (r1 < Nq) { float2 o = {acc[nt][2]+b0, acc[nt][3]+b1};
                       *(float2*)(g_att + r1*64 + col) = o; }
    }
}

// ============================================================================
// ffn2: g_hid = relu(g_att @ lin1_w^T + lin1_b)
// ============================================================================
#define SM_F2 ((64 * 264 + 64 * PADK) * 4)
__global__ __launch_bounds__(256) void ffn2_mma(const float* __restrict__ lin1_b)
{
    extern __shared__ unsigned sm[];
    unsigned* s_W = sm;              // [64][264]
    unsigned* s_A = sm + 64 * 264;   // [64][68]
    const int tid = threadIdx.x, lane = tid & 31, w = tid >> 5;
    const int g = lane >> 2, tig = lane & 3;
    const int mr = (w & 3) * 16, nbase = (w >> 2) * 128;
    const int rows0 = blockIdx.x * 64;

    for (int i = tid; i < 4224; i += 256)
        ((uint4*)s_W)[i] = ((const uint4*)g_W1)[i];
    for (int i = tid; i < 64 * 64; i += 256) {
        int r = i >> 6, c = i & 63, row = rows0 + r;
        s_A[r * PADK + c] = f2tf32(row < Nq ? g_att[row * 64 + c] : 0.f);
    }
    __syncthreads();

    float acc[16][4];
    #pragma unroll
    for (int nt = 0; nt < 16; ++nt)
        #pragma unroll
        for (int j = 0; j < 4; ++j) acc[nt][j] = 0.f;

    #pragma unroll
    for (int ks = 0; ks < 8; ++ks) {
        int k0 = ks * 8;
        unsigned a0 = s_A[(mr+g)*PADK + k0 + tig];
        unsigned a1 = s_A[(mr+g+8)*PADK + k0 + tig];
        unsigned a2 = s_A[(mr+g)*PADK + k0 + tig + 4];
        unsigned a3 = s_A[(mr+g+8)*PADK + k0 + tig + 4];
        #pragma unroll
        for (int nt = 0; nt < 16; ++nt) {
            unsigned b0 = s_W[(k0+tig)*264 + nbase + nt*8 + g];
            unsigned b1 = s_W[(k0+tig+4)*264 + nbase + nt*8 + g];
            mma_tf32(acc[nt][0], acc[nt][1], acc[nt][2], acc[nt][3], a0, a1, a2, a3, b0, b1);
        }
    }
    #pragma unroll
    for (int nt = 0; nt < 16; ++nt) {
        int col = nbase + nt*8 + 2*tig;
        float b0 = lin1_b[col], b1 = lin1_b[col+1];
        int r0 = rows0 + mr + g, r1 = r0 + 8;
        if (r0 < Nq) { float2 o = {fmaxf(acc[nt][0]+b0, 0.f), fmaxf(acc[nt][1]+b1, 0.f)};
                       *(float2*)(g_hid + r0*256 + col) = o; }
        if (r1 < Nq) { float2 o = {fmaxf(acc[nt][2]+b0, 0.f), fmaxf(acc[nt][3]+b1, 0.f)};
                       *(float2*)(g_hid + r1*256 + col) = o; }
    }
}

// ============================================================================
// ffn3: g_x = g_att + g_hid @ lin2_w^T + lin2_b, BN1 stats
// ============================================================================
#define SM_F3 ((256 * 72 + 128 * PADK + 128) * 4)
__global__ __launch_bounds__(256) void ffn3_mma(const float* __restrict__ lin2_b)
{
    extern __shared__ unsigned sm[];
    unsigned* s_W = sm;               // [256][72]
    unsigned* s_A = sm + 256 * 72;    // [128][68]
    float* s_ps = (float*)(s_A + 128 * PADK);
    float* s_pq = s_ps + 64;
    const int tid = threadIdx.x, lane = tid & 31, w = tid >> 5;
    const int g = lane >> 2, tig = lane & 3, mr = w * 16;
    const int rows0 = blockIdx.x * 128;

    if (tid < 64) { s_ps[tid] = 0.f; s_pq[tid] = 0.f; }
    for (int i = tid; i < 4608; i += 256)
        ((uint4*)s_W)[i] = ((const uint4*)g_W2)[i];

    float acc[8][4] = {};
    for (int kc = 0; kc < 4; ++kc) {
        __syncthreads();
        for (int i = tid; i < 128 * 64; i += 256) {
            int r = i >> 6, c = i & 63, row = rows0 + r;
            s_A[r * PADK + c] = f2tf32(row < Nq ? g_hid[row * 256 + kc * 64 + c] : 0.f);
        }
        __syncthreads();
        #pragma unroll
        for (int ks = 0; ks < 8; ++ks) {
            int k0 = ks * 8;
            unsigned a0 = s_A[(mr+g)*PADK + k0 + tig];
            unsigned a1 = s_A[(mr+g+8)*PADK + k0 + tig];
            unsigned a2 = s_A[(mr+g)*PADK + k0 + tig + 4];
            unsigned a3 = s_A[(mr+g+8)*PADK + k0 + tig + 4];
            int kw = kc * 64 + k0;
            #pragma unroll
            for (int nt = 0; nt < 8; ++nt) {
                unsigned b0 = s_W[(kw+tig)*72 + nt*8 + g];
                unsigned b1 = s_W[(kw+tig+4)*72 + nt*8 + g];
                mma_tf32(acc[nt][0], acc[nt][1], acc[nt][2], acc[nt][3], a0, a1, a2, a3, b0, b1);
            }
        }
    }

    #pragma unroll
    for (int nt = 0; nt < 8; ++nt) {
        int col = nt*8 + 2*tig;
        float b0 = lin2_b[col], b1 = lin2_b[col+1];
        int r0 = rows0 + mr + g, r1 = r0 + 8;
        bool v0 = r0 < Nq, v1 = r1 < Nq;
        float2 a0r = v0 ? *(const float2*)(g_att + r0*64 + col) : make_float2(0.f, 0.f);
        float2 a1r = v1 ? *(const float2*)(g_att + r1*64 + col) : make_float2(0.f, 0.f);
        float x00 = acc[nt][0] + b0 + a0r.x, x01 = acc[nt][1] + b1 + a0r.y;
        float x10 = acc[nt][2] + b0 + a1r.x, x11 = acc[nt][3] + b1 + a1r.y;
        if (v0) { float2 o = {x00, x01}; *(float2*)(g_x + r0*64 + col) = o; }
        if (v1) { float2 o = {x10, x11}; *(float2*)(g_x + r1*64 + col) = o; }
        float m00 = v0 ? x00 : 0.f, m01 = v0 ? x01 : 0.f;
        float m10 = v1 ? x10 : 0.f, m11 = v1 ? x11 : 0.f;
        float se = m00 + m10,                 so = m01 + m11;
        float sq = m00*m00 + m10*m10,         qo = m01*m01 + m11*m11;
        #pragma unroll
        for (int o = 16; o >= 4; o >>= 1) {
            se += __shfl_down_sync(0xffffffffu, se, o);
            so += __shfl_down_sync(0xffffffffu, so, o);
            sq += __shfl_down_sync(0xffffffffu, sq, o);
            qo += __shfl_down_sync(0xffffffffu, qo, o);
        }
        if (lane < 4) {
            atomicAdd(&s_ps[col], se);  atomicAdd(&s_pq[col], sq);
            atomicAdd(&s_ps[col+1], so); atomicAdd(&s_pq[col+1], qo);
        }
    }
    __syncthreads();
    if (tid < 64) {
        atomicAdd(&g_sum1[tid], (double)s_ps[tid]);
        atomicAdd(&g_sq1[tid],  (double)s_pq[tid]);
    }
}

// ============================================================================
// proj: g_z = BN1(g_x) @ outl_w^T + outl_b, BN2 stats. Inlines BN1 finalize.
// ============================================================================
#define SM_P ((64 * 72 + 128 * PADK + 256) * 4)
__global__ __launch_bounds__(256) void proj_mma(
    const float* __restrict__ outl_b,
    const float* __restrict__ norm_g, const float* __restrict__ norm_b)
{
    extern __shared__ unsigned sm[];
    unsigned* s_W = sm;
    unsigned* s_A = sm + 64 * 72;
    float* s_ps = (float*)(s_A + 128 * PADK);
    float* s_pq = s_ps + 64;
    float* s_mu = s_pq + 64;
    float* s_rs = s_mu + 64;
    const int tid = threadIdx.x, lane = tid & 31, w = tid >> 5;
    const int g = lane >> 2, tig = lane & 3, mr = w * 16;
    const int rows0 = blockIdx.x * 128;

    if (tid < 64) {
        s_ps[tid] = 0.f; s_pq[tid] = 0.f;
        double m = g_sum1[tid] / (double)Nq;
        double v = g_sq1[tid] / (double)Nq - m * m;
        if (v < 0) v = 0;
        s_mu[tid] = (float)m;
        s_rs[tid] = (float)(1.0 / sqrt(v + 1e-5));
    }
    for (int i = tid; i < 1152; i += 256)
        ((uint4*)s_W)[i] = ((const uint4*)g_Wl)[i];
    __syncthreads();
    {
        const int c = tid & 63;
        const float mu = s_mu[c], rs = s_rs[c], ga = norm_g[c], be = norm_b[c];
        for (int i = tid; i < 128 * 64; i += 256) {
            int r = i >> 6, row = rows0 + r;
            float v = 0.f;
            if (row < Nq) v = (g_x[row * 64 + c] - mu) * rs * ga + be;
            s_A[r * PADK + c] = f2tf32(v);
        }
    }
    __syncthreads();

    float acc[8][4] = {};
    #pragma unroll
    for (int ks = 0; ks < 8; ++ks) {
        int k0 = ks * 8;
        unsigned a0 = s_A[(mr+g)*PADK + k0 + tig];
        unsigned a1 = s_A[(mr+g+8)*PADK + k0 + tig];
        unsigned a2 = s_A[(mr+g)*PADK + k0 + tig + 4];
        unsigned a3 = s_A[(mr+g+8)*PADK + k0 + tig + 4];
        #pragma unroll
        for (int nt = 0; nt < 8; ++nt) {
            unsigned b0 = s_W[(k0+tig)*72 + nt*8 + g];
            unsigned b1 = s_W[(k0+tig+4)*72 + nt*8 + g];
            mma_tf32(acc[nt][0], acc[nt][1], acc[nt][2], acc[nt][3], a0, a1, a2, a3, b0, b1);
        }
    }
    #pragma unroll
    for (int nt = 0; nt < 8; ++nt) {
        int col = nt*8 + 2*tig;
        float b0 = outl_b[col], b1 = outl_b[col+1];
        int r0 = rows0 + mr + g, r1 = r0 + 8;
        bool v0 = r0 < Nq, v1 = r1 < Nq;
        float x00 = acc[nt][0] + b0, x01 = acc[nt][1] + b1;
        float x10 = acc[nt][2] + b0, x11 = acc[nt][3] + b1;
        if (v0) { float2 o = {x00, x01}; *(float2*)(g_z + r0*64 + col) = o; }
        if (v1) { float2 o = {x10, x11}; *(float2*)(g_z + r1*64 + col) = o; }
        float m00 = v0 ? x00 : 0.f, m01 = v0 ? x01 : 0.f;
        float m10 = v1 ? x10 : 0.f, m11 = v1 ? x11 : 0.f;
        float se = m00 + m10,                 so = m01 + m11;
        float sq = m00*m00 + m10*m10,         qo = m01*m01 + m11*m11;
        #pragma unroll
        for (int o = 16; o >= 4; o >>= 1) {
            se += __shfl_down_sync(0xffffffffu, se, o);
            so += __shfl_down_sync(0xffffffffu, so, o);
            sq += __shfl_down_sync(0xffffffffu, sq, o);
            qo += __shfl_down_sync(0xffffffffu, qo, o);
        }
        if (lane < 4) {
            atomicAdd(&s_ps[col], se);  atomicAdd(&s_pq[col], sq);
            atomicAdd(&s_ps[col+1], so); atomicAdd(&s_pq[col+1], qo);
        }
    }
    __syncthreads();
    if (tid < 64) {
        atomicAdd(&g_sum2[tid], (double)s_ps[tid]);
        atomicAdd(&g_sq2[tid],  (double)s_pq[tid]);
    }
}

__global__ void finalize2_kernel() {
    int t = threadIdx.x;
    if (t < 64) {
        double m = g_sum2[t] / (double)Nq;
        double v = g_sq2[t] / (double)Nq - m * m;
        if (v < 0) v = 0;
        g_mu2[t] = (float)m;
        g_rs2[t] = (float)(1.0 / sqrt(v + 1e-5));
    }
}

__global__ void final_kernel(float* __restrict__ out,
                             const float* __restrict__ obn_g,
                             const float* __restrict__ obn_b)
{
    int i = blockIdx.x * 256 + threadIdx.x;
    if (i < Nq * 64) {
        int o = i & 63;
        float v = (g_z[i] - g_mu2[o]) * g_rs2[o] * obn_g[o] + obn_b[o];
        out[i] = fmaxf(v, 0.f);
    }
}

extern "C" void kernel_launch(void* const* d_in, const int* in_sizes, int n_in,
                              void* d_out, int out_size) {
    const float* vf     = (const float*)d_in[0];
    const float* vc     = (const float*)d_in[1];
    const float* qcoord = (const float*)d_in[2];
    const int*   kidx   = (const int*)  d_in[3];
    const float* q_w    = (const float*)d_in[4];
    const float* q_b    = (const float*)d_in[5];
    const float* kpos_w = (const float*)d_in[6];
    const float* kpos_b = (const float*)d_in[7];
    const float* in_w   = (const float*)d_in[8];
    const float* in_b   = (const float*)d_in[9];
    const float* out_w  = (const float*)d_in[10];
    const float* out_b  = (const float*)d_in[11];
    const float* lin1_w = (const float*)d_in[12];
    const float* lin1_b = (const float*)d_in[13];
    const float* lin2_w = (const float*)d_in[14];
    const float* lin2_b = (const float*)d_in[15];
    const float* norm_g = (const float*)d_in[16];
    const float* norm_b = (const float*)d_in[17];
    const float* outl_w = (const float*)d_in[18];
    const float* outl_b = (const float*)d_in[19];
    const float* obn_g  = (const float*)d_in[20];
    const float* obn_b  = (const float*)d_in[21];
    float* out = (float*)d_out;

    cudaFuncSetAttribute(attn_kernel, cudaFuncAttributeMaxDynamicSharedMemorySize, SMEM_ATTN);
    cudaFuncSetAttribute(qproj_mma,   cudaFuncAttributeMaxDynamicSharedMemorySize, SM_Q);
    cudaFuncSetAttribute(ffn1_mma,    cudaFuncAttributeMaxDynamicSharedMemorySize, SM_F1);
    cudaFuncSetAttribute(ffn2_mma,    cudaFuncAttributeMaxDynamicSharedMemorySize, SM_F2);
    cudaFuncSetAttribute(ffn3_mma,    cudaFuncAttributeMaxDynamicSharedMemorySize, SM_F3);
    cudaFuncSetAttribute(proj_mma,    cudaFuncAttributeMaxDynamicSharedMemorySize, SM_P);

    const int RB = (Nq + 127) / 128;    // 157

    prep_kernel<<<13, 256>>>(in_w, out_w, lin1_w, lin2_w, outl_w);   // launch 1
    zero_stats<<<1, 64>>>();                                         // launch 2
    qproj_mma<<<RB, 256, SM_Q>>>(qcoord, q_w, q_b, in_b);            // launch 3
    attn_kernel<<<Nq / 4, 384, SMEM_ATTN>>>(vf, vc, qcoord, kidx,
                                            kpos_w, kpos_b, in_b);   // launch 4 (ncu)
    ffn1_mma<<<RB, 256, SM_F1>>>(out_b);
    ffn2_mma<<<(Nq + 63) / 64, 256, SM_F2>>>(lin1_b);
    ffn3_mma<<<RB, 256, SM_F3>>>(lin2_b);
    proj_mma<<<RB, 256, SM_P>>>(outl_b, norm_g, norm_b);
    finalize2_kernel<<<1, 64>>>();
    final_kernel<<<(Nq * 64 + 255) / 256, 256>>>(out, obn_g, obn_b);
}

// round 17
// speedup vs baseline: 1.3920x; 1.0243x over previous
#include <cuda_runtime.h>
#include <math.h>

#define Nq   20000
#define KK   48
#define PADK 68
#define BST  132   // B2 ull row stride (conflict-free)

// ---- scratch ----
__device__ float  g_q[Nq * 64];
__device__ float  g_ctx[Nq * 64];
__device__ float  g_att[Nq * 64];
__device__ float  g_hid[Nq * 256];
__device__ float  g_x[Nq * 64];
__device__ float  g_z[Nq * 64];
__device__ double g_sum1[64], g_sq1[64];
__device__ double g_sum2[64], g_sq2[64];
// pre-converted tf32 weights (padded layouts)
__device__ unsigned long long g_B2d[32 * BST];
__device__ unsigned g_Wq[64 * 72];
__device__ unsigned g_Wo[64 * 72];
__device__ unsigned g_W1[64 * 264];
__device__ unsigned g_W2[256 * 72];
__device__ unsigned g_Wl[64 * 72];

__device__ __forceinline__ unsigned f2tf32(float x) {
    unsigned r; asm("cvt.rna.tf32.f32 %0, %1;" : "=r"(r) : "f"(x)); return r;
}
__device__ __forceinline__ void mma_tf32(float& d0, float& d1, float& d2, float& d3,
                                         unsigned a0, unsigned a1, unsigned a2, unsigned a3,
                                         unsigned b0, unsigned b1) {
    asm volatile("mma.sync.aligned.m16n8k8.row.col.f32.tf32.tf32.f32 "
                 "{%0,%1,%2,%3}, {%4,%5,%6,%7}, {%8,%9}, {%0,%1,%2,%3};"
                 : "+f"(d0), "+f"(d1), "+f"(d2), "+f"(d3)
                 : "r"(a0), "r"(a1), "r"(a2), "r"(a3), "r"(b0), "r"(b1));
}

// ============================================================================
// prep: weight conversion + stats zeroing (14 blocks)
// ============================================================================
__global__ __launch_bounds__(256) void prep_kernel(
    const float* __restrict__ in_w,  const float* __restrict__ out_w,
    const float* __restrict__ lin1_w, const float* __restrict__ lin2_w,
    const float* __restrict__ outl_w)
{
    const int tid = threadIdx.x, b = blockIdx.x;
    if (b == 0) {
        for (int i = tid; i < 4096; i += 256) {
            int n = i >> 6, k = i & 63;
            g_Wq[k * 72 + n] = f2tf32(in_w[n * 64 + k]);
        }
    } else if (b <= 2) {             // B2: in_w rows 64..191 (K|V), packed pairs
        for (int i = (b - 1) * 4096 + tid; i < b * 4096; i += 256) {
            int n = i >> 6, k = i & 63;
            int ks = k >> 3, rem = k & 7, tg = rem & 3, slot = rem >> 2;
            ((unsigned*)g_B2d)[(((ks*4+tg)*BST) + n) * 2 + slot] = f2tf32(in_w[4096 + i]);
        }
    } else if (b == 3) {
        for (int i = tid; i < 4096; i += 256) {
            int n = i >> 6, k = i & 63;
            g_Wo[k * 72 + n] = f2tf32(out_w[n * 64 + k]);
        }
    } else if (b <= 7) {
        for (int i = (b - 4) * 4096 + tid; i < (b - 3) * 4096; i += 256) {
            int n = i >> 6, k = i & 63;
            g_W1[k * 264 + n] = f2tf32(lin1_w[n * 64 + k]);
        }
    } else if (b <= 11) {
        for (int i = (b - 8) * 4096 + tid; i < (b - 7) * 4096; i += 256) {
            int k = i >> 6, n = i & 63;
            g_W2[k * 72 + n] = f2tf32(lin2_w[n * 256 + k]);
        }
    } else if (b == 12) {
        for (int i = tid; i < 4096; i += 256) {
            int n = i >> 6, k = i & 63;
            g_Wl[k * 72 + n] = f2tf32(outl_w[n * 64 + k]);
        }
    } else {                          // zero stats
        if (tid < 64) {
            g_sum1[tid] = 0.0; g_sq1[tid] = 0.0;
            g_sum2[tid] = 0.0; g_sq2[tid] = 0.0;
        }
    }
}

// ============================================================================
// qproj
// ============================================================================
#define SM_Q ((64 * 72 + 128 * PADK) * 4)
__global__ __launch_bounds__(256) void qproj_mma(
    const float* __restrict__ qc, const float* __restrict__ q_w, const float* __restrict__ q_b,
    const float* __restrict__ in_b)
{
    extern __shared__ unsigned sm[];
    unsigned* s_W = sm;
    unsigned* s_A = sm + 64 * 72;
    const int tid = threadIdx.x, lane = tid & 31, w = tid >> 5;
    const int g = lane >> 2, tig = lane & 3, mr = w * 16;
    const int rows0 = blockIdx.x * 128;

    for (int i = tid; i < 1152; i += 256)
        ((uint4*)s_W)[i] = ((const uint4*)g_Wq)[i];
    {
        const int c = tid & 63;
        const float w0 = q_w[c*3], w1 = q_w[c*3+1], w2 = q_w[c*3+2], b = q_b[c];
        for (int i = tid; i < 128 * 64; i += 256) {
            int r = i >> 6, row = rows0 + r;
            float v = 0.f;
            if (row < Nq)
                v = fmaxf(b + w0*qc[row*3] + w1*qc[row*3+1] + w2*qc[row*3+2], 0.f);
            s_A[r * PADK + c] = f2tf32(v);
        }
    }
    __syncthreads();

    float acc[8][4] = {};
    #pragma unroll
    for (int ks = 0; ks < 8; ++ks) {
        int k0 = ks * 8;
        unsigned a0 = s_A[(mr+g)*PADK + k0 + tig];
        unsigned a1 = s_A[(mr+g+8)*PADK + k0 + tig];
        unsigned a2 = s_A[(mr+g)*PADK + k0 + tig + 4];
        unsigned a3 = s_A[(mr+g+8)*PADK + k0 + tig + 4];
        #pragma unroll
        for (int nt = 0; nt < 8; ++nt) {
            unsigned b0 = s_W[(k0+tig)*72 + nt*8 + g];
            unsigned b1 = s_W[(k0+tig+4)*72 + nt*8 + g];
            mma_tf32(acc[nt][0], acc[nt][1], acc[nt][2], acc[nt][3], a0, a1, a2, a3, b0, b1);
        }
    }
    #pragma unroll
    for (int nt = 0; nt < 8; ++nt) {
        int col = nt*8 + 2*tig;
        float b0 = in_b[col], b1 = in_b[col+1];
        int r0 = rows0 + mr + g, r1 = r0 + 8;
        if (r0 < Nq) { float2 o = {(acc[nt][0]+b0)*0.25f, (acc[nt][1]+b1)*0.25f};
                       *(float2*)(g_q + r0*64 + col) = o; }
        if (r1 < Nq) { float2 o = {(acc[nt][2]+b0)*0.25f, (acc[nt][3]+b1)*0.25f};
                       *(float2*)(g_q + r1*64 + col) = o; }
    }
}

// ============================================================================
// attention kernel: 4 queries/block, 384 threads (12 warps), N-split across
// warps (0-5 K half, 6-11 V half, M=32 rows each), 2 CTAs/SM.
// Softmax fused into ctx (warp-local).
// ============================================================================
#define SMEM_ATTN ((13056 + 2*BST*32 + 256 + 768 + 576 + 192) * 4)
__global__ __launch_bounds__(384, 2) void attn_kernel(
    const float* __restrict__ vf,     const float* __restrict__ vc,
    const float* __restrict__ qc,     const int*   __restrict__ kidx,
    const float* __restrict__ kpos_w, const float* __restrict__ kpos_b,
    const float* __restrict__ in_b)
{
    extern __shared__ unsigned smu[];
    unsigned* s_kfu = smu;                         // [192][68] tf32 A (alias vp float)
    unsigned* s_B2  = smu + 192 * PADK;            // ull[32][132] = 8448 words
    float*    s_q   = (float*)(s_B2 + 2*BST*32);   // 256
    float*    s_sc  = s_q + 256;                   // 768
    float*    s_rel = s_sc + 768;                  // 576
    int*      s_idx = (int*)(s_rel + 576);         // 192

    const int tid  = threadIdx.x;
    const int lane = tid & 31;
    const int w    = tid >> 5;            // 0..11
    const int n0   = blockIdx.x * 4;

    // ---- staging ----
    for (int i = tid; i < 2112; i += 384)
        ((uint4*)s_B2)[i] = ((const uint4*)g_B2d)[i];
    if (tid < 192) {
        int q = tid / KK, kk = tid - q * KK;
        int n = n0 + q;
        int idx = kidx[n * KK + kk];
        s_idx[tid] = idx;
        int safe = idx < 0 ? 0 : idx;
        s_rel[tid*3+0] = vc[safe*3+0] - qc[n*3+0];
        s_rel[tid*3+1] = vc[safe*3+1] - qc[n*3+1];
        s_rel[tid*3+2] = vc[safe*3+2] - qc[n*3+2];
    }
    if (tid < 256) s_q[tid] = g_q[(n0 + (tid >> 6)) * 64 + (tid & 63)];
    __syncthreads();

    // ---- gather key features (tf32, float2-vectorized) ----
    {
        const int c2 = (tid & 31) * 2;
        const float ka0 = kpos_w[c2*3],   ka1 = kpos_w[c2*3+1], ka2 = kpos_w[c2*3+2];
        const float kb0 = kpos_w[c2*3+3], kb1 = kpos_w[c2*3+4], kb2 = kpos_w[c2*3+5];
        const float kba = kpos_b[c2], kbb = kpos_b[c2+1];
        for (int e = tid; e < 192 * 32; e += 384) {
            int kg = e >> 5;
            int idx = s_idx[kg]; if (idx < 0) idx = 0;
            float2 f = *(const float2*)(vf + idx * 64 + c2);
            float r0 = s_rel[kg*3], r1 = s_rel[kg*3+1], r2 = s_rel[kg*3+2];
            float p0 = kba + ka0*r0 + ka1*r1 + ka2*r2;
            float p1 = kbb + kb0*r0 + kb1*r1 + kb2*r2;
            uint2 o = { f2tf32(f.x + fmaxf(p0, 0.f)), f2tf32(f.y + fmaxf(p1, 0.f)) };
            *(uint2*)(s_kfu + kg * PADK + c2) = o;
        }
    }
    __syncthreads();

    const int g    = lane >> 2;
    const int tig  = lane & 3;
    const int half = (w >= 6);
    const int mw   = w - half * 6;
    const int mr   = mw * 32;
    const int cb   = half * 64;
    const unsigned long long* B2u = (const unsigned long long*)s_B2;

    float acc0[8][4], acc1[8][4];
    #pragma unroll
    for (int nt = 0; nt < 8; ++nt) {
        int cc = 8*nt + 2*tig;
        float b0 = in_b[64 + cb + cc], b1 = in_b[64 + cb + cc + 1];
        acc0[nt][0] = b0; acc0[nt][1] = b1; acc0[nt][2] = b0; acc0[nt][3] = b1;
        acc1[nt][0] = b0; acc1[nt][1] = b1; acc1[nt][2] = b0; acc1[nt][3] = b1;
    }
    #pragma unroll
    for (int ks = 0; ks < 8; ++ks) {
        const int k0 = ks * 8;
        unsigned a00 = s_kfu[(mr+g)*PADK + k0 + tig];
        unsigned a01 = s_kfu[(mr+g+8)*PADK + k0 + tig];
        unsigned a02 = s_kfu[(mr+g)*PADK + k0 + tig + 4];
        unsigned a03 = s_kfu[(mr+g+8)*PADK + k0 + tig + 4];
        unsigned a10 = s_kfu[(mr+g+16)*PADK + k0 + tig];
        unsigned a11 = s_kfu[(mr+g+24)*PADK + k0 + tig];
        unsigned a12 = s_kfu[(mr+g+16)*PADK + k0 + tig + 4];
        unsigned a13 = s_kfu[(mr+g+24)*PADK + k0 + tig + 4];
        const unsigned long long* bp = B2u + (ks*4 + tig) * BST + g + cb;
        #pragma unroll
        for (int nt = 0; nt < 8; ++nt) {
            unsigned long long pv = bp[nt * 8];
            unsigned b0 = (unsigned)pv, b1 = (unsigned)(pv >> 32);
            mma_tf32(acc0[nt][0], acc0[nt][1], acc0[nt][2], acc0[nt][3],
                     a00, a01, a02, a03, b0, b1);
            mma_tf32(acc1[nt][0], acc1[nt][1], acc1[nt][2], acc1[nt][3],
                     a10, a11, a12, a13, b0, b1);
        }
    }
    __syncthreads();   // all A reads complete before vp aliases kf

    if (half == 0) {
        #pragma unroll
        for (int t = 0; t < 2; ++t) {
            int r1 = mr + 16*t + g, r2 = r1 + 8;
            int q1 = r1 / KK, kk1 = r1 - q1 * KK;
            int q2 = r2 / KK, kk2 = r2 - q2 * KK;
            #pragma unroll
            for (int h = 0; h < 4; ++h) {
                int nA = 2*h, nB = 2*h + 1;
                int cA = 8*nA + 2*tig, cB = 8*nB + 2*tig;
                float qA0 = s_q[q1*64+cA], qA1 = s_q[q1*64+cA+1];
                float qB0 = s_q[q1*64+cB], qB1 = s_q[q1*64+cB+1];
                float qC0 = s_q[q2*64+cA], qC1 = s_q[q2*64+cA+1];
                float qD0 = s_q[q2*64+cB], qD1 = s_q[q2*64+cB+1];
                float s0, s1;
                if (t == 0) {
                    s0 = acc0[nA][0]*qA0 + acc0[nA][1]*qA1 + acc0[nB][0]*qB0 + acc0[nB][1]*qB1;
                    s1 = acc0[nA][2]*qC0 + acc0[nA][3]*qC1 + acc0[nB][2]*qD0 + acc0[nB][3]*qD1;
                } else {
                    s0 = acc1[nA][0]*qA0 + acc1[nA][1]*qA1 + acc1[nB][0]*qB0 + acc1[nB][1]*qB1;
                    s1 = acc1[nA][2]*qC0 + acc1[nA][3]*qC1 + acc1[nB][2]*qD0 + acc1[nB][3]*qD1;
                }
                s0 += __shfl_xor_sync(0xffffffffu, s0, 1);
                s0 += __shfl_xor_sync(0xffffffffu, s0, 2);
                s1 += __shfl_xor_sync(0xffffffffu, s1, 1);
                s1 += __shfl_xor_sync(0xffffffffu, s1, 2);
                if (tig == 0) {
                    s_sc[(q1*4+h)*48 + kk1] = (s_idx[r1] < 0) ? -1e30f : s0;
                    s_sc[(q2*4+h)*48 + kk2] = (s_idx[r2] < 0) ? -1e30f : s1;
                }
            }
        }
    } else {
        float* s_vp = (float*)s_kfu;
        #pragma unroll
        for (int t = 0; t < 2; ++t) {
            int r1 = mr + 16*t + g, r2 = r1 + 8;
            #pragma unroll
            for (int nt = 0; nt < 8; ++nt) {
                int cc = 8*nt + 2*tig;
                float2 o1, o2;
                if (t == 0) { o1 = make_float2(acc0[nt][0], acc0[nt][1]);
                              o2 = make_float2(acc0[nt][2], acc0[nt][3]); }
                else        { o1 = make_float2(acc1[nt][0], acc1[nt][1]);
                              o2 = make_float2(acc1[nt][2], acc1[nt][3]); }
                *(float2*)(s_vp + r1*PADK + cc) = o1;
                *(float2*)(s_vp + r2*PADK + cc) = o2;
            }
        }
    }
    __syncthreads();

    // ---- fused softmax + ctx: warp w<8 owns (q = w>>1, c-half = w&1) ----
    if (w < 8) {
        const int q  = w >> 1;
        const int ch = w & 1;
        #pragma unroll
        for (int hh = 0; hh < 2; ++hh) {
            int r = q * 4 + ch * 2 + hh;
            float* sc = s_sc + r * 48;
            float v0 = sc[lane];
            float v1 = (lane < 16) ? sc[32 + lane] : -1e30f;
            float m = fmaxf(v0, v1);
            #pragma unroll
            for (int o = 16; o > 0; o >>= 1) m = fmaxf(m, __shfl_xor_sync(0xffffffffu, m, o));
            float e0 = __expf(v0 - m);
            float e1 = (lane < 16) ? __expf(v1 - m) : 0.f;
            float s = e0 + e1;
            #pragma unroll
            for (int o = 16; o > 0; o >>= 1) s += __shfl_xor_sync(0xffffffffu, s, o);
            float inv = 1.f / s;
            sc[lane] = e0 * inv;
            if (lane < 16) sc[32 + lane] = e1 * inv;
        }
        __syncwarp();
        const float* s_vp = (const float*)s_kfu;
        int c = ch * 32 + lane, h = c >> 4;
        const float* a  = s_sc + (q * 4 + h) * 48;
        const float* vp = s_vp + (q * 48) * PADK + c;
        float acc2 = 0.f;
        #pragma unroll 8
        for (int kk = 0; kk < KK; ++kk) acc2 = fmaf(a[kk], vp[kk * PADK], acc2);
        g_ctx[(n0 + q) * 64 + c] = acc2;
    }
}

// ============================================================================
// ffn1: g_att = g_ctx @ out_w^T + out_b
// ============================================================================
#define SM_F1 ((64 * 72 + 128 * PADK) * 4)
__global__ __launch_bounds__(256) void ffn1_mma(const float* __restrict__ out_b)
{
    extern __shared__ unsigned sm[];
    unsigned* s_W = sm;
    unsigned* s_A = sm + 64 * 72;
    const int tid = threadIdx.x, lane = tid & 31, w = tid >> 5;
    const int g = lane >> 2, tig = lane & 3, mr = w * 16;
    const int rows0 = blockIdx.x * 128;

    for (int i = tid; i < 1152; i += 256)
        ((uint4*)s_W)[i] = ((const uint4*)g_Wo)[i];
    for (int i = tid; i < 128 * 64; i += 256) {
        int r = i >> 6, c = i & 63, row = rows0 + r;
        s_A[r * PADK + c] = f2tf32(row < Nq ? g_ctx[row * 64 + c] : 0.f);
    }
    __syncthreads();

    float acc[8][4] = {};
    #pragma unroll
    for (int ks = 0; ks < 8; ++ks) {
        int k0 = ks * 8;
        unsigned a0 = s_A[(mr+g)*PADK + k0 + tig];
        unsigned a1 = s_A[(mr+g+8)*PADK + k0 + tig];
        unsigned a2 = s_A[(mr+g)*PADK + k0 + tig + 4];
        unsigned a3 = s_A[(mr+g+8)*PADK + k0 + tig + 4];
        #pragma unroll
        for (int nt = 0; nt < 8; ++nt) {
            unsigned b0 = s_W[(k0+tig)*72 + nt*8 + g];
            unsigned b1 = s_W[(k0+tig+4)*72 + nt*8 + g];
            mma_tf32(acc[nt][0], acc[nt][1], acc[nt][2], acc[nt][3], a0, a1, a2, a3, b0, b1);
        }
    }
    #pragma unroll
    for (int nt = 0; nt < 8; ++nt) {
        int col = nt*8 + 2*tig;
        float b0 = out_b[col], b1 = out_b[col+1];
        int r0 = rows0 + mr + g, r1 = r0 + 8;
        if (r0 < Nq) { float2 o = {acc[nt][0]+b0, acc[nt][1]+b1};
                       *(float2*)(g_att + r0*64 + col) = o; }
        if (r1 < Nq) { float2 o = {acc[nt][2]+b0, acc[nt][3]+b1};
                       *(float2*)(g_att + r1*64 + col) = o; }
    }
}

// ============================================================================
// ffn2: g_hid = relu(g_att @ lin1_w^T + lin1_b)
// ============================================================================
#define SM_F2 ((64 * 264 + 64 * PADK) * 4)
__global__ __launch_bounds__(256) void ffn2_mma(const float* __restrict__ lin1_b)
{
    extern __shared__ unsigned sm[];
    unsigned* s_W = sm;              // [64][264]
    unsigned* s_A = sm + 64 * 264;   // [64][68]
    const int tid = threadIdx.x, lane = tid & 31, w = tid >> 5;
    const int g = lane >> 2, tig = lane & 3;
    const int mr = (w & 3) * 16, nbase = (w >> 2) * 128;
    const int rows0 = blockIdx.x * 64;

    for (int i = tid; i < 4224; i += 256)
        ((uint4*)s_W)[i] = ((const uint4*)g_W1)[i];
    for (int i = tid; i < 64 * 64; i += 256) {
        int r = i >> 6, c = i & 63, row = rows0 + r;
        s_A[r * PADK + c] = f2tf32(row < Nq ? g_att[row * 64 + c] : 0.f);
    }
    __syncthreads();

    float acc[16][4];
    #pragma unroll
    for (int nt = 0; nt < 16; ++nt)
        #pragma unroll
        for (int j = 0; j < 4; ++j) acc[nt][j] = 0.f;

    #pragma unroll
    for (int ks = 0; ks < 8; ++ks) {
        int k0 = ks * 8;
        unsigned a0 = s_A[(mr+g)*PADK + k0 + tig];
        unsigned a1 = s_A[(mr+g+8)*PADK + k0 + tig];
        unsigned a2 = s_A[(mr+g)*PADK + k0 + tig + 4];
        unsigned a3 = s_A[(mr+g+8)*PADK + k0 + tig + 4];
        #pragma unroll
        for (int nt = 0; nt < 16; ++nt) {
            unsigned b0 = s_W[(k0+tig)*264 + nbase + nt*8 + g];
            unsigned b1 = s_W[(k0+tig+4)*264 + nbase + nt*8 + g];
            mma_tf32(acc[nt][0], acc[nt][1], acc[nt][2], acc[nt][3], a0, a1, a2, a3, b0, b1);
        }
    }
    #pragma unroll
    for (int nt = 0; nt < 16; ++nt) {
        int col = nbase + nt*8 + 2*tig;
        float b0 = lin1_b[col], b1 = lin1_b[col+1];
        int r0 = rows0 + mr + g, r1 = r0 + 8;
        if (r0 < Nq) { float2 o = {fmaxf(acc[nt][0]+b0, 0.f), fmaxf(acc[nt][1]+b1, 0.f)};
                       *(float2*)(g_hid + r0*256 + col) = o; }
        if (r1 < Nq) { float2 o = {fmaxf(acc[nt][2]+b0, 0.f), fmaxf(acc[nt][3]+b1, 0.f)};
                       *(float2*)(g_hid + r1*256 + col) = o; }
    }
}

// ============================================================================
// ffn3: g_x = g_att + g_hid @ lin2_w^T + lin2_b, BN1 stats
// ============================================================================
#define SM_F3 ((256 * 72 + 128 * PADK + 128) * 4)
__global__ __launch_bounds__(256) void ffn3_mma(const float* __restrict__ lin2_b)
{
    extern __shared__ unsigned sm[];
    unsigned* s_W = sm;               // [256][72]
    unsigned* s_A = sm + 256 * 72;    // [128][68]
    float* s_ps = (float*)(s_A + 128 * PADK);
    float* s_pq = s_ps + 64;
    const int tid = threadIdx.x, lane = tid & 31, w = tid >> 5;
    const int g = lane >> 2, tig = lane & 3, mr = w * 16;
    const int rows0 = blockIdx.x * 128;

    if (tid < 64) { s_ps[tid] = 0.f; s_pq[tid] = 0.f; }
    for (int i = tid; i < 4608; i += 256)
        ((uint4*)s_W)[i] = ((const uint4*)g_W2)[i];

    float acc[8][4] = {};
    for (int kc = 0; kc < 4; ++kc) {
        __syncthreads();
        for (int i = tid; i < 128 * 64; i += 256) {
            int r = i >> 6, c = i & 63, row = rows0 + r;
            s_A[r * PADK + c] = f2tf32(row < Nq ? g_hid[row * 256 + kc * 64 + c] : 0.f);
        }
        __syncthreads();
        #pragma unroll
        for (int ks = 0; ks < 8; ++ks) {
            int k0 = ks * 8;
            unsigned a0 = s_A[(mr+g)*PADK + k0 + tig];
            unsigned a1 = s_A[(mr+g+8)*PADK + k0 + tig];
            unsigned a2 = s_A[(mr+g)*PADK + k0 + tig + 4];
            unsigned a3 = s_A[(mr+g+8)*PADK + k0 + tig + 4];
            int kw = kc * 64 + k0;
            #pragma unroll
            for (int nt = 0; nt < 8; ++nt) {
                unsigned b0 = s_W[(kw+tig)*72 + nt*8 + g];
                unsigned b1 = s_W[(kw+tig+4)*72 + nt*8 + g];
                mma_tf32(acc[nt][0], acc[nt][1], acc[nt][2], acc[nt][3], a0, a1, a2, a3, b0, b1);
            }
        }
    }

    #pragma unroll
    for (int nt = 0; nt < 8; ++nt) {
        int col = nt*8 + 2*tig;
        float b0 = lin2_b[col], b1 = lin2_b[col+1];
        int r0 = rows0 + mr + g, r1 = r0 + 8;
        bool v0 = r0 < Nq, v1 = r1 < Nq;
        float2 a0r = v0 ? *(const float2*)(g_att + r0*64 + col) : make_float2(0.f, 0.f);
        float2 a1r = v1 ? *(const float2*)(g_att + r1*64 + col) : make_float2(0.f, 0.f);
        float x00 = acc[nt][0] + b0 + a0r.x, x01 = acc[nt][1] + b1 + a0r.y;
        float x10 = acc[nt][2] + b0 + a1r.x, x11 = acc[nt][3] + b1 + a1r.y;
        if (v0) { float2 o = {x00, x01}; *(float2*)(g_x + r0*64 + col) = o; }
        if (v1) { float2 o = {x10, x11}; *(float2*)(g_x + r1*64 + col) = o; }
        float m00 = v0 ? x00 : 0.f, m01 = v0 ? x01 : 0.f;
        float m10 = v1 ? x10 : 0.f, m11 = v1 ? x11 : 0.f;
        float se = m00 + m10,                 so = m01 + m11;
        float sq = m00*m00 + m10*m10,         qo = m01*m01 + m11*m11;
        #pragma unroll
        for (int o = 16; o >= 4; o >>= 1) {
            se += __shfl_down_sync(0xffffffffu, se, o);
            so += __shfl_down_sync(0xffffffffu, so, o);
            sq += __shfl_down_sync(0xffffffffu, sq, o);
            qo += __shfl_down_sync(0xffffffffu, qo, o);
        }
        if (lane < 4) {
            atomicAdd(&s_ps[col], se);  atomicAdd(&s_pq[col], sq);
            atomicAdd(&s_ps[col+1], so); atomicAdd(&s_pq[col+1], qo);
        }
    }
    __syncthreads();
    if (tid < 64) {
        atomicAdd(&g_sum1[tid], (double)s_ps[tid]);
        atomicAdd(&g_sq1[tid],  (double)s_pq[tid]);
    }
}

// ============================================================================
// proj: g_z = BN1(g_x) @ outl_w^T + outl_b, BN2 stats. Inlines BN1 finalize.
// ============================================================================
#define SM_P ((64 * 72 + 128 * PADK + 256) * 4)
__global__ __launch_bounds__(256) void proj_mma(
    const float* __restrict__ outl_b,
    const float* __restrict__ norm_g, const float* __restrict__ norm_b)
{
    extern __shared__ unsigned sm[];
    unsigned* s_W = sm;
    unsigned* s_A = sm + 64 * 72;
    float* s_ps = (float*)(s_A + 128 * PADK);
    float* s_pq = s_ps + 64;
    float* s_mu = s_pq + 64;
    float* s_rs = s_mu + 64;
    const int tid = threadIdx.x, lane = tid & 31, w = tid >> 5;
    const int g = lane >> 2, tig = lane & 3, mr = w * 16;
    const int rows0 = blockIdx.x * 128;

    if (tid < 64) {
        s_ps[tid] = 0.f; s_pq[tid] = 0.f;
        double m = g_sum1[tid] / (double)Nq;
        double v = g_sq1[tid] / (double)Nq - m * m;
        if (v < 0) v = 0;
        s_mu[tid] = (float)m;
        s_rs[tid] = (float)(1.0 / sqrt(v + 1e-5));
    }
    for (int i = tid; i < 1152; i += 256)
        ((uint4*)s_W)[i] = ((const uint4*)g_Wl)[i];
    __syncthreads();
    {
        const int c = tid & 63;
        const float mu = s_mu[c], rs = s_rs[c], ga = norm_g[c], be = norm_b[c];
        for (int i = tid; i < 128 * 64; i += 256) {
            int r = i >> 6, row = rows0 + r;
            float v = 0.f;
            if (row < Nq) v = (g_x[row * 64 + c] - mu) * rs * ga + be;
            s_A[r * PADK + c] = f2tf32(v);
        }
    }
    __syncthreads();

    float acc[8][4] = {};
    #pragma unroll
    for (int ks = 0; ks < 8; ++ks) {
        int k0 = ks * 8;
        unsigned a0 = s_A[(mr+g)*PADK + k0 + tig];
        unsigned a1 = s_A[(mr+g+8)*PADK + k0 + tig];
        unsigned a2 = s_A[(mr+g)*PADK + k0 + tig + 4];
        unsigned a3 = s_A[(mr+g+8)*PADK + k0 + tig + 4];
        #pragma unroll
        for (int nt = 0; nt < 8; ++nt) {
            unsigned b0 = s_W[(k0+tig)*72 + nt*8 + g];
            unsigned b1 = s_W[(k0+tig+4)*72 + nt*8 + g];
            mma_tf32(acc[nt][0], acc[nt][1], acc[nt][2], acc[nt][3], a0, a1, a2, a3, b0, b1);
        }
    }
    #pragma unroll
    for (int nt = 0; nt < 8; ++nt) {
        int col = nt*8 + 2*tig;
        float b0 = outl_b[col], b1 = outl_b[col+1];
        int r0 = rows0 + mr + g, r1 = r0 + 8;
        bool v0 = r0 < Nq, v1 = r1 < Nq;
        float x00 = acc[nt][0] + b0, x01 = acc[nt][1] + b1;
        float x10 = acc[nt][2] + b0, x11 = acc[nt][3] + b1;
        if (v0) { float2 o = {x00, x01}; *(float2*)(g_z + r0*64 + col) = o; }
        if (v1) { float2 o = {x10, x11}; *(float2*)(g_z + r1*64 + col) = o; }
        float m00 = v0 ? x00 : 0.f, m01 = v0 ? x01 : 0.f;
        float m10 = v1 ? x10 : 0.f, m11 = v1 ? x11 : 0.f;
        float se = m00 + m10,                 so = m01 + m11;
        float sq = m00*m00 + m10*m10,         qo = m01*m01 + m11*m11;
        #pragma unroll
        for (int o = 16; o >= 4; o >>= 1) {
            se += __shfl_down_sync(0xffffffffu, se, o);
            so += __shfl_down_sync(0xffffffffu, so, o);
            sq += __shfl_down_sync(0xffffffffu, sq, o);
            qo += __shfl_down_sync(0xffffffffu, qo, o);
        }
        if (lane < 4) {
            atomicAdd(&s_ps[col], se);  atomicAdd(&s_pq[col], sq);
            atomicAdd(&s_ps[col+1], so); atomicAdd(&s_pq[col+1], qo);
        }
    }
    __syncthreads();
    if (tid < 64) {
        atomicAdd(&g_sum2[tid], (double)s_ps[tid]);
        atomicAdd(&g_sq2[tid],  (double)s_pq[tid]);
    }
}

// ============================================================================
// final: BN2 + relu -> out. Fat blocks (157), inlined BN2 finalize, float4.
// ============================================================================
__global__ __launch_bounds__(256) void final_kernel(
    float* __restrict__ out,
    const float* __restrict__ obn_g, const float* __restrict__ obn_b)
{
    __shared__ float s_scale[64], s_shift[64];
    const int tid = threadIdx.x;
    if (tid < 64) {
        double m = g_sum2[tid] / (double)Nq;
        double v = g_sq2[tid] / (double)Nq - m * m;
        if (v < 0) v = 0;
        float mu = (float)m;
        float rs = (float)(1.0 / sqrt(v + 1e-5));
        float sc = rs * obn_g[tid];
        s_scale[tid] = sc;
        s_shift[tid] = obn_b[tid] - mu * sc;
    }
    __syncthreads();
    const int base4 = blockIdx.x * 2048;     // float4 units (8192 floats/block)
    #pragma unroll
    for (int k = 0; k < 8; ++k) {
        int i4 = base4 + k * 256 + tid;
        if (i4 * 4 < Nq * 64) {
            float4 v = *(const float4*)(g_z + i4 * 4);
            int c0 = (i4 * 4) & 63;
            float4 o;
            o.x = fmaxf(v.x * s_scale[c0]     + s_shift[c0],     0.f);
            o.y = fmaxf(v.y * s_scale[c0 + 1] + s_shift[c0 + 1], 0.f);
            o.z = fmaxf(v.z * s_scale[c0 + 2] + s_shift[c0 + 2], 0.f);
            o.w = fmaxf(v.w * s_scale[c0 + 3] + s_shift[c0 + 3], 0.f);
            *(float4*)(out + i4 * 4) = o;
        }
    }
}

extern "C" void kernel_launch(void* const* d_in, const int* in_sizes, int n_in,
                              void* d_out, int out_size) {
    const float* vf     = (const float*)d_in[0];
    const float* vc     = (const float*)d_in[1];
    const float* qcoord = (const float*)d_in[2];
    const int*   kidx   = (const int*)  d_in[3];
    const float* q_w    = (const float*)d_in[4];
    const float* q_b    = (const float*)d_in[5];
    const float* kpos_w = (const float*)d_in[6];
    const float* kpos_b = (const float*)d_in[7];
    const float* in_w   = (const float*)d_in[8];
    const float* in_b   = (const float*)d_in[9];
    const float* out_w  = (const float*)d_in[10];
    const float* out_b  = (const float*)d_in[11];
    const float* lin1_w = (const float*)d_in[12];
    const float* lin1_b = (const float*)d_in[13];
    const float* lin2_w = (const float*)d_in[14];
    const float* lin2_b = (const float*)d_in[15];
    const float* norm_g = (const float*)d_in[16];
    const float* norm_b = (const float*)d_in[17];
    const float* outl_w = (const float*)d_in[18];
    const float* outl_b = (const float*)d_in[19];
    const float* obn_g  = (const float*)d_in[20];
    const float* obn_b  = (const float*)d_in[21];
    float* out = (float*)d_out;

    cudaFuncSetAttribute(attn_kernel, cudaFuncAttributeMaxDynamicSharedMemorySize, SMEM_ATTN);
    cudaFuncSetAttribute(qproj_mma,   cudaFuncAttributeMaxDynamicSharedMemorySize, SM_Q);
    cudaFuncSetAttribute(ffn1_mma,    cudaFuncAttributeMaxDynamicSharedMemorySize, SM_F1);
    cudaFuncSetAttribute(ffn2_mma,    cudaFuncAttributeMaxDynamicSharedMemorySize, SM_F2);
    cudaFuncSetAttribute(ffn3_mma,    cudaFuncAttributeMaxDynamicSharedMemorySize, SM_F3);
    cudaFuncSetAttribute(proj_mma,    cudaFuncAttributeMaxDynamicSharedMemorySize, SM_P);

    const int RB = (Nq + 127) / 128;    // 157

    prep_kernel<<<14, 256>>>(in_w, out_w, lin1_w, lin2_w, outl_w);   // launch 1 (+stats zero)
    qproj_mma<<<RB, 256, SM_Q>>>(qcoord, q_w, q_b, in_b);            // launch 2
    attn_kernel<<<Nq / 4, 384, SMEM_ATTN>>>(vf, vc, qcoord, kidx,
                                            kpos_w, kpos_b, in_b);   // launch 3
    ffn1_mma<<<RB, 256, SM_F1>>>(out_b);
    ffn2_mma<<<(Nq + 63) / 64, 256, SM_F2>>>(lin1_b);
    ffn3_mma<<<RB, 256, SM_F3>>>(lin2_b);
    proj_mma<<<RB, 256, SM_P>>>(outl_b, norm_g, norm_b);
    final_kernel<<<RB, 256>>>(out, obn_g, obn_b);
}